// round 1
// baseline (speedup 1.0000x reference)
#include <cuda_runtime.h>
#include <math.h>

#define BB   4
#define SEQ  1024
#define DIMC 1024
#define NH   16
#define DHD  64
#define ROWS (BB * SEQ)      // 4096
#define FPAD 68              // padded smem row stride (floats), keeps float4 alignment

// ---------------- scratch (device globals: allocation-guard safe) ----------------
__device__ float g_Qp[ROWS * DIMC];
__device__ float g_Kp[ROWS * DIMC];
__device__ float g_Vp[ROWS * DIMC];
__device__ float g_attn[ROWS * DIMC];
__device__ float g_X[ROWS * DIMC];
__device__ float g_Hb[ROWS * DIMC];
__device__ int   g_maskQ[ROWS];
__device__ int   g_maskK[ROWS];

// ---------------- mask canonicalization (dtype auto-detect) ----------------
// bool masks may arrive as int32 {0,1}, float {0,1.0f}, or raw bytes.
// int32/float cases: every 4-byte word is in {0,1,0x3F800000}. Byte case:
// random bytes make that pattern essentially impossible over 32 words.
__device__ __forceinline__ int mask_is_bytes(const unsigned int* w) {
    bool wordlike = true;
#pragma unroll
    for (int i = 0; i < 32; i++) {
        unsigned int v = w[i];
        if (v != 0u && v != 1u && v != 0x3F800000u) wordlike = false;
    }
    return wordlike ? 0 : 1;
}

__global__ void prep_mask_kernel(const void* mq, const void* mk) {
    int bq = mask_is_bytes((const unsigned int*)mq);
    int bk = mask_is_bytes((const unsigned int*)mk);
    for (int i = threadIdx.x; i < ROWS; i += blockDim.x) {
        int vq = bq ? (((const unsigned char*)mq)[i] != 0)
                    : (((const unsigned int*)mq)[i] != 0u);
        int vk = bk ? (((const unsigned char*)mk)[i] != 0)
                    : (((const unsigned int*)mk)[i] != 0u);
        g_maskQ[i] = vq;
        g_maskK[i] = vk;
    }
}

// ---------------- SGEMM: C[M,N] = A[M,K] * B[N,K]^T (both row-major) ----------------
// 128x128 block tile, BK=8, 256 threads, 8x8 per thread.
__global__ __launch_bounds__(256) void sgemm_nt(const float* __restrict__ A,
                                                const float* __restrict__ B,
                                                float* __restrict__ C,
                                                int M, int N, int K) {
    __shared__ float As[8][128];
    __shared__ float Bs[8][128];
    const int tid = threadIdx.x;
    const int bm = blockIdx.y * 128;
    const int bn = blockIdx.x * 128;
    const int lrow = tid >> 1;           // 0..127
    const int lcol = (tid & 1) << 2;     // 0 or 4
    const float* Ag = A + (size_t)(bm + lrow) * K + lcol;
    const float* Bg = B + (size_t)(bn + lrow) * K + lcol;
    const int tx = tid & 15;
    const int ty = tid >> 4;

    float acc[8][8];
#pragma unroll
    for (int i = 0; i < 8; i++)
#pragma unroll
        for (int j = 0; j < 8; j++) acc[i][j] = 0.f;

    for (int k0 = 0; k0 < K; k0 += 8) {
        float4 a4 = *(const float4*)(Ag + k0);
        float4 b4 = *(const float4*)(Bg + k0);
        __syncthreads();
        As[lcol + 0][lrow] = a4.x; As[lcol + 1][lrow] = a4.y;
        As[lcol + 2][lrow] = a4.z; As[lcol + 3][lrow] = a4.w;
        Bs[lcol + 0][lrow] = b4.x; Bs[lcol + 1][lrow] = b4.y;
        Bs[lcol + 2][lrow] = b4.z; Bs[lcol + 3][lrow] = b4.w;
        __syncthreads();
#pragma unroll
        for (int k = 0; k < 8; k++) {
            float ar[8], br[8];
            *(float4*)(ar)     = *(const float4*)(&As[k][ty * 4]);
            *(float4*)(ar + 4) = *(const float4*)(&As[k][64 + ty * 4]);
            *(float4*)(br)     = *(const float4*)(&Bs[k][tx * 4]);
            *(float4*)(br + 4) = *(const float4*)(&Bs[k][64 + tx * 4]);
#pragma unroll
            for (int i = 0; i < 8; i++)
#pragma unroll
                for (int j = 0; j < 8; j++)
                    acc[i][j] = fmaf(ar[i], br[j], acc[i][j]);
        }
    }
#pragma unroll
    for (int ih = 0; ih < 2; ih++)
#pragma unroll
        for (int ii = 0; ii < 4; ii++) {
            int r = bm + ih * 64 + ty * 4 + ii;
#pragma unroll
            for (int jh = 0; jh < 2; jh++) {
                int c = bn + jh * 64 + tx * 4;
                float4 v = make_float4(acc[ih * 4 + ii][jh * 4 + 0],
                                       acc[ih * 4 + ii][jh * 4 + 1],
                                       acc[ih * 4 + ii][jh * 4 + 2],
                                       acc[ih * 4 + ii][jh * 4 + 3]);
                *(float4*)(&C[(size_t)r * N + c]) = v;
            }
        }
}

// ---------------- flash attention: per (b, h, 64-query tile) ----------------
// S = Qh Kh^T / 32, key-mask -> -1e38 (exp underflows to exact 0),
// online softmax, O accumulated in registers, divide by l at the end.
// Masked-q rows produce garbage here; downstream layernorm masking zeroes them.
__global__ __launch_bounds__(256) void flash_kernel(const float* __restrict__ Qp,
                                                    const float* __restrict__ Kp,
                                                    const float* __restrict__ Vp,
                                                    float* __restrict__ Out) {
    extern __shared__ float smf[];
    float* Qs   = smf;
    float* Ks   = Qs + 64 * FPAD;
    float* Vs   = Ks + 64 * FPAD;
    float* Ss   = Vs + 64 * FPAD;
    float* mrow = Ss + 64 * FPAD;
    float* lrow = mrow + 64;
    float* crow = lrow + 64;

    const int tid = threadIdx.x;
    const int b = blockIdx.z, h = blockIdx.y;
    const int q0 = blockIdx.x * 64;
    const int tx = tid & 15, ty = tid >> 4;
    const int lr = tid >> 2;            // loader row 0..63
    const int lc = (tid & 3) * 16;      // loader col base

    // load Q tile [64 x 64]
    {
        const float* src = Qp + ((size_t)(b * SEQ + q0 + lr)) * DIMC + h * DHD + lc;
        float* dst = Qs + lr * FPAD + lc;
#pragma unroll
        for (int t = 0; t < 4; t++)
            *(float4*)(dst + t * 4) = *(const float4*)(src + t * 4);
    }
    if (tid < 64) { mrow[tid] = -1e38f; lrow[tid] = 0.f; }

    float o[4][4];
#pragma unroll
    for (int i = 0; i < 4; i++)
#pragma unroll
        for (int j = 0; j < 4; j++) o[i][j] = 0.f;

    for (int kt = 0; kt < SEQ / 64; kt++) {
        const int k0 = kt * 64;
        __syncthreads();   // previous P*V done (also fences Q load on kt==0)
        {
            const float* sK = Kp + ((size_t)(b * SEQ + k0 + lr)) * DIMC + h * DHD + lc;
            const float* sV = Vp + ((size_t)(b * SEQ + k0 + lr)) * DIMC + h * DHD + lc;
            float* dK = Ks + lr * FPAD + lc;
            float* dV = Vs + lr * FPAD + lc;
#pragma unroll
            for (int t = 0; t < 4; t++) {
                *(float4*)(dK + t * 4) = *(const float4*)(sK + t * 4);
                *(float4*)(dV + t * 4) = *(const float4*)(sV + t * 4);
            }
        }
        __syncthreads();

        // S = Q K^T (4x4 per thread), scale, key-mask
        int mk[4];
#pragma unroll
        for (int j = 0; j < 4; j++) mk[j] = g_maskK[b * SEQ + k0 + tx * 4 + j];

        float s[4][4];
#pragma unroll
        for (int i = 0; i < 4; i++)
#pragma unroll
            for (int j = 0; j < 4; j++) s[i][j] = 0.f;

#pragma unroll 4
        for (int d = 0; d < DHD; d += 4) {
            float4 qv[4], kv[4];
#pragma unroll
            for (int i = 0; i < 4; i++) qv[i] = *(const float4*)&Qs[(ty * 4 + i) * FPAD + d];
#pragma unroll
            for (int j = 0; j < 4; j++) kv[j] = *(const float4*)&Ks[(tx * 4 + j) * FPAD + d];
#pragma unroll
            for (int i = 0; i < 4; i++)
#pragma unroll
                for (int j = 0; j < 4; j++) {
                    s[i][j] = fmaf(qv[i].x, kv[j].x, s[i][j]);
                    s[i][j] = fmaf(qv[i].y, kv[j].y, s[i][j]);
                    s[i][j] = fmaf(qv[i].z, kv[j].z, s[i][j]);
                    s[i][j] = fmaf(qv[i].w, kv[j].w, s[i][j]);
                }
        }
#pragma unroll
        for (int i = 0; i < 4; i++)
#pragma unroll
            for (int j = 0; j < 4; j++)
                Ss[(ty * 4 + i) * FPAD + tx * 4 + j] = mk[j] ? -1e38f : s[i][j] * 0.03125f;
        __syncthreads();

        // online softmax row pass (one thread per row)
        if (tid < 64) {
            float* sr = Ss + tid * FPAD;
            float mo = mrow[tid], mn = mo;
#pragma unroll 8
            for (int j = 0; j < 64; j++) mn = fmaxf(mn, sr[j]);
            float cc = __expf(mo - mn);
            float ls = 0.f;
#pragma unroll 8
            for (int j = 0; j < 64; j++) {
                float p = __expf(sr[j] - mn);
                sr[j] = p;
                ls += p;
            }
            lrow[tid] = lrow[tid] * cc + ls;
            mrow[tid] = mn;
            crow[tid] = cc;
        }
        __syncthreads();

        // O = O*c + P V
        float cr[4];
#pragma unroll
        for (int i = 0; i < 4; i++) cr[i] = crow[ty * 4 + i];
#pragma unroll
        for (int i = 0; i < 4; i++)
#pragma unroll
            for (int j = 0; j < 4; j++) o[i][j] *= cr[i];

        for (int kk = 0; kk < 64; kk++) {
            float4 v4 = *(const float4*)&Vs[kk * FPAD + tx * 4];
#pragma unroll
            for (int i = 0; i < 4; i++) {
                float p = Ss[(ty * 4 + i) * FPAD + kk];
                o[i][0] = fmaf(p, v4.x, o[i][0]);
                o[i][1] = fmaf(p, v4.y, o[i][1]);
                o[i][2] = fmaf(p, v4.z, o[i][2]);
                o[i][3] = fmaf(p, v4.w, o[i][3]);
            }
        }
    }

#pragma unroll
    for (int i = 0; i < 4; i++) {
        float li = 1.f / lrow[ty * 4 + i];
        float4 v = make_float4(o[i][0] * li, o[i][1] * li, o[i][2] * li, o[i][3] * li);
        *(float4*)&Out[((size_t)(b * SEQ + q0 + ty * 4 + i)) * DIMC + h * DHD + tx * 4] = v;
    }
}

// ---------------- layernorm helpers ----------------
__device__ __forceinline__ void block_reduce2(float& s, float& ss) {
    __shared__ float r1[8], r2[8];
#pragma unroll
    for (int o = 16; o > 0; o >>= 1) {
        s  += __shfl_xor_sync(0xffffffffu, s, o);
        ss += __shfl_xor_sync(0xffffffffu, ss, o);
    }
    int w = threadIdx.x >> 5;
    if ((threadIdx.x & 31) == 0) { r1[w] = s; r2[w] = ss; }
    __syncthreads();
    s = 0.f; ss = 0.f;
#pragma unroll
    for (int i = 0; i < 8; i++) { s += r1[i]; ss += r2[i]; }
}

__global__ __launch_bounds__(256) void ln1_kernel(const float* __restrict__ A,
                                                  const float* __restrict__ Bv,
                                                  const float* __restrict__ gm,
                                                  const float* __restrict__ be,
                                                  float* __restrict__ X) {
    const int row = blockIdx.x;
    float* xo = X + (size_t)row * DIMC;
    if (g_maskQ[row]) {
        for (int i = threadIdx.x; i < DIMC; i += 256) xo[i] = 0.f;
        return;
    }
    const float* a  = A + (size_t)row * DIMC;
    const float* bv = Bv + (size_t)row * DIMC;
    float vals[4];
    float s = 0.f, ss = 0.f;
#pragma unroll
    for (int t = 0; t < 4; t++) {
        int i = threadIdx.x + t * 256;
        float v = a[i] + bv[i];
        vals[t] = v; s += v; ss += v * v;
    }
    block_reduce2(s, ss);
    float mean = s * (1.f / DIMC);
    float var  = ss * (1.f / DIMC) - mean * mean;
    float rstd = rsqrtf(var + 1e-5f);
#pragma unroll
    for (int t = 0; t < 4; t++) {
        int i = threadIdx.x + t * 256;
        xo[i] = (vals[t] - mean) * rstd * gm[i] + be[i];
    }
}

__device__ __forceinline__ float gelu_exact(float x) {
    return 0.5f * x * (1.f + erff(x * 0.70710678118654752f));
}

__global__ __launch_bounds__(256) void final_kernel(const float* __restrict__ X,
                                                    const float* __restrict__ Hx,
                                                    const float* __restrict__ gm,
                                                    const float* __restrict__ be,
                                                    float* __restrict__ out) {
    const int row = blockIdx.x;
    float* o = out + (size_t)row * DIMC;
    if (g_maskQ[row]) {
        for (int i = threadIdx.x; i < DIMC; i += 256) o[i] = 0.f;
        return;
    }
    const float* x = X + (size_t)row * DIMC;
    const float* hv = Hx + (size_t)row * DIMC;
    float vals[4];
    float s = 0.f, ss = 0.f;
#pragma unroll
    for (int t = 0; t < 4; t++) {
        int i = threadIdx.x + t * 256;
        float v = x[i] + gelu_exact(hv[i]);
        vals[t] = v; s += v; ss += v * v;
    }
    block_reduce2(s, ss);
    float mean = s * (1.f / DIMC);
    float var  = ss * (1.f / DIMC) - mean * mean;
    float rstd = rsqrtf(var + 1e-5f);
#pragma unroll
    for (int t = 0; t < 4; t++) {
        int i = threadIdx.x + t * 256;
        o[i] = (vals[t] - mean) * rstd * gm[i] + be[i];
    }
}

// ---------------- launch ----------------
extern "C" void kernel_launch(void* const* d_in, const int* in_sizes, int n_in,
                              void* d_out, int out_size) {
    const float* Q    = (const float*)d_in[0];
    const float* K    = (const float*)d_in[1];
    const float* V    = (const float*)d_in[2];
    const float* Wq   = (const float*)d_in[3];
    const float* Wk   = (const float*)d_in[4];
    const float* Wv   = (const float*)d_in[5];
    const float* Wo   = (const float*)d_in[6];
    const float* ln1g = (const float*)d_in[7];
    const float* ln1b = (const float*)d_in[8];
    const float* ln2g = (const float*)d_in[9];
    const float* ln2b = (const float*)d_in[10];
    const void*  mq   = d_in[11];
    const void*  mk   = d_in[12];
    float* out = (float*)d_out;

    void *pQp, *pKp, *pVp, *pAt, *pX, *pH;
    cudaGetSymbolAddress(&pQp, g_Qp);
    cudaGetSymbolAddress(&pKp, g_Kp);
    cudaGetSymbolAddress(&pVp, g_Vp);
    cudaGetSymbolAddress(&pAt, g_attn);
    cudaGetSymbolAddress(&pX,  g_X);
    cudaGetSymbolAddress(&pH,  g_Hb);

    prep_mask_kernel<<<1, 256>>>(mq, mk);

    dim3 gg(DIMC / 128, ROWS / 128);  // (8, 32)
    sgemm_nt<<<gg, 256>>>(Q, Wq, (float*)pQp, ROWS, DIMC, DIMC);
    sgemm_nt<<<gg, 256>>>(K, Wk, (float*)pKp, ROWS, DIMC, DIMC);
    sgemm_nt<<<gg, 256>>>(V, Wv, (float*)pVp, ROWS, DIMC, DIMC);

    size_t shmem = (size_t)(4 * 64 * FPAD + 3 * 64) * sizeof(float);  // 70400 B
    cudaFuncSetAttribute(flash_kernel, cudaFuncAttributeMaxDynamicSharedMemorySize,
                         (int)shmem);
    flash_kernel<<<dim3(SEQ / 64, NH, BB), 256, shmem>>>(
        (const float*)pQp, (const float*)pKp, (const float*)pVp, (float*)pAt);

    ln1_kernel<<<ROWS, 256>>>((const float*)pQp, (const float*)pAt, ln1g, ln1b,
                              (float*)pX);

    sgemm_nt<<<gg, 256>>>((const float*)pX, Wo, (float*)pH, ROWS, DIMC, DIMC);

    final_kernel<<<ROWS, 256>>>((const float*)pX, (const float*)pH, ln2g, ln2b, out);
}

// round 5
// speedup vs baseline: 1.3990x; 1.3990x over previous
#include <cuda_runtime.h>
#include <cuda_bf16.h>
#include <math.h>
#include <stdint.h>

#define BB   4
#define SEQ  1024
#define DIMC 1024
#define NH   16
#define DHD  64
#define ROWS (BB * SEQ)      // 4096
#define FPAD 68              // flash smem pad

// ---------------- scratch (device globals: allocation-guard safe) ----------------
__device__ float g_Qp[ROWS * DIMC];
__device__ float g_Kp[ROWS * DIMC];
__device__ float g_Vp[ROWS * DIMC];
__device__ float g_attn[ROWS * DIMC];
__device__ float g_X[ROWS * DIMC];
__device__ float g_Hb[ROWS * DIMC];
__device__ int   g_maskQ[ROWS];
__device__ int   g_maskK[ROWS];
// split-bf16 operands
__device__ __nv_bfloat16 g_Ah[ROWS * DIMC];
__device__ __nv_bfloat16 g_Al[ROWS * DIMC];
__device__ __nv_bfloat16 g_Wh[4][DIMC * DIMC];
__device__ __nv_bfloat16 g_Wl[4][DIMC * DIMC];

// ---------------- PTX helpers (base compute_103-safe only) ----------------
__device__ __forceinline__ uint32_t smem_u32(const void* p) {
    uint32_t a;
    asm("{ .reg .u64 t; cvta.to.shared.u64 t, %1; cvt.u32.u64 %0, t; }"
        : "=r"(a) : "l"(p));
    return a;
}

#define CP_ASYNC16(dst, src) \
    asm volatile("cp.async.cg.shared.global [%0], [%1], 16;" \
                 :: "r"(dst), "l"(src) : "memory")
#define CP_COMMIT()  asm volatile("cp.async.commit_group;" ::: "memory")
#define CP_WAIT(n)   asm volatile("cp.async.wait_group %0;" :: "n"(n) : "memory")

#define LDSM4(r0, r1, r2, r3, addr) \
    asm volatile("ldmatrix.sync.aligned.m8n8.x4.shared.b16 {%0,%1,%2,%3}, [%4];" \
                 : "=r"(r0), "=r"(r1), "=r"(r2), "=r"(r3) : "r"(addr))

#define MMA_BF16(d, a, b0, b1) \
    asm volatile("mma.sync.aligned.m16n8k16.row.col.f32.bf16.bf16.f32 " \
                 "{%0,%1,%2,%3}, {%4,%5,%6,%7}, {%8,%9}, {%0,%1,%2,%3};" \
                 : "+f"((d)[0]), "+f"((d)[1]), "+f"((d)[2]), "+f"((d)[3]) \
                 : "r"((a)[0]), "r"((a)[1]), "r"((a)[2]), "r"((a)[3]), \
                   "r"(b0), "r"(b1))

// ---------------- mask canonicalization ----------------
__device__ __forceinline__ int mask_is_bytes(const unsigned int* w) {
    bool wordlike = true;
#pragma unroll
    for (int i = 0; i < 32; i++) {
        unsigned int v = w[i];
        if (v != 0u && v != 1u && v != 0x3F800000u) wordlike = false;
    }
    return wordlike ? 0 : 1;
}

__global__ void prep_mask_kernel(const void* mq, const void* mk) {
    int bq = mask_is_bytes((const unsigned int*)mq);
    int bk = mask_is_bytes((const unsigned int*)mk);
    for (int i = threadIdx.x; i < ROWS; i += blockDim.x) {
        int vq = bq ? (((const unsigned char*)mq)[i] != 0)
                    : (((const unsigned int*)mq)[i] != 0u);
        int vk = bk ? (((const unsigned char*)mk)[i] != 0)
                    : (((const unsigned int*)mk)[i] != 0u);
        g_maskQ[i] = vq;
        g_maskK[i] = vk;
    }
}

// ---------------- fp32 -> (bf16 hi, bf16 lo) split ----------------
__global__ __launch_bounds__(256) void conv_hilo(const float* __restrict__ x,
                                                 __nv_bfloat16* __restrict__ hi,
                                                 __nv_bfloat16* __restrict__ lo,
                                                 int n4) {
    int i = blockIdx.x * blockDim.x + threadIdx.x;
    if (i >= n4) return;
    float4 v = ((const float4*)x)[i];
    __nv_bfloat16 h0 = __float2bfloat16(v.x);
    __nv_bfloat16 h1 = __float2bfloat16(v.y);
    __nv_bfloat16 h2 = __float2bfloat16(v.z);
    __nv_bfloat16 h3 = __float2bfloat16(v.w);
    __nv_bfloat16 l0 = __float2bfloat16(v.x - __bfloat162float(h0));
    __nv_bfloat16 l1 = __float2bfloat16(v.y - __bfloat162float(h1));
    __nv_bfloat16 l2 = __float2bfloat16(v.z - __bfloat162float(h2));
    __nv_bfloat16 l3 = __float2bfloat16(v.w - __bfloat162float(h3));
    ((__nv_bfloat162*)hi)[2 * i]     = __nv_bfloat162(h0, h1);
    ((__nv_bfloat162*)hi)[2 * i + 1] = __nv_bfloat162(h2, h3);
    ((__nv_bfloat162*)lo)[2 * i]     = __nv_bfloat162(l0, l1);
    ((__nv_bfloat162*)lo)[2 * i + 1] = __nv_bfloat162(l2, l3);
}

// ---------------- mma.sync split-bf16 GEMM ----------------
// C[4096,1024] = A * B^T (B stored [N,K] row-major).
// C = Ahi*Bhi + Ahi*Blo + Alo*Bhi.
// CTA tile 128x128, warp tile 32x64 (4M x 2N warps), K-chunk 32, cp.async dbuf.
#define MST   40                      // smem halves per row (80B, conflict-free)
#define TILEB (128 * MST * 2)         // 10240 B per tile
#define BUFB  (4 * TILEB)             // Ah,Al,Bh,Bl
#define NCH   (DIMC / 32)             // 32 chunks

__device__ __forceinline__ void gemm_load_chunk(
    uint32_t sbase, const __nv_bfloat16* __restrict__ Ah,
    const __nv_bfloat16* __restrict__ Al, const __nv_bfloat16* __restrict__ Bh,
    const __nv_bfloat16* __restrict__ Bl, int bm, int bn, int k0, int tid) {
#pragma unroll
    for (int h = 0; h < 2; h++) {
        int idx = tid + h * 256;            // 0..511
        int r = idx >> 2, q = idx & 3;
        uint32_t doff = (uint32_t)(r * (MST * 2) + q * 16);
        size_t ga = ((size_t)(bm + r) << 10) + k0 + (q << 3);
        size_t gb = ((size_t)(bn + r) << 10) + k0 + (q << 3);
        CP_ASYNC16(sbase + doff,             Ah + ga);
        CP_ASYNC16(sbase + TILEB + doff,     Al + ga);
        CP_ASYNC16(sbase + 2 * TILEB + doff, Bh + gb);
        CP_ASYNC16(sbase + 3 * TILEB + doff, Bl + gb);
    }
}

__global__ __launch_bounds__(256) void gemm_mma3(
    const __nv_bfloat16* __restrict__ Ah, const __nv_bfloat16* __restrict__ Al,
    const __nv_bfloat16* __restrict__ Bh, const __nv_bfloat16* __restrict__ Bl,
    float* __restrict__ C) {
    extern __shared__ char sm[];
    const uint32_t base = smem_u32(sm);
    const int tid = threadIdx.x;
    const int bm = blockIdx.y * 128;
    const int bn = blockIdx.x * 128;
    const int warp = tid >> 5, lane = tid & 31;
    const int wm = warp & 3;          // M warp 0..3 (rows wm*32..+32)
    const int wn = warp >> 2;         // N warp 0..1 (cols wn*64..+64)

    float acc[2][8][4];
#pragma unroll
    for (int i = 0; i < 2; i++)
#pragma unroll
        for (int j = 0; j < 8; j++)
#pragma unroll
            for (int k = 0; k < 4; k++) acc[i][j][k] = 0.f;

    gemm_load_chunk(base, Ah, Al, Bh, Bl, bm, bn, 0, tid);
    CP_COMMIT();

    // precomputed ldmatrix lane offsets
    const int a_row = (lane & 15);              // + mf*16 + wm*32
    const int a_k   = (lane >> 4) * 8;          // + ks*16
    const int b_row = (lane & 7) + ((lane >> 4) << 3);  // + nf4*16 + wn*64
    const int b_k   = ((lane >> 3) & 1) * 8;    // + ks*16

    for (int c = 0; c < NCH; c++) {
        if (c + 1 < NCH) {
            gemm_load_chunk(base + ((c + 1) & 1) * BUFB, Ah, Al, Bh, Bl,
                            bm, bn, (c + 1) * 32, tid);
            CP_COMMIT();
            CP_WAIT(1);
        } else {
            CP_WAIT(0);
        }
        __syncthreads();

        const uint32_t bu = base + (c & 1) * BUFB;
        const uint32_t tAh = bu;
        const uint32_t tAl = bu + TILEB;
        const uint32_t tBh = bu + 2 * TILEB;
        const uint32_t tBl = bu + 3 * TILEB;

#pragma unroll
        for (int ks = 0; ks < 2; ks++) {
            uint32_t ah[2][4], al[2][4];
            const int kk = ks * 16 + a_k;
#pragma unroll
            for (int mf = 0; mf < 2; mf++) {
                uint32_t ra = (uint32_t)((wm * 32 + mf * 16 + a_row) * (MST * 2) + kk * 2);
                LDSM4(ah[mf][0], ah[mf][1], ah[mf][2], ah[mf][3], tAh + ra);
                LDSM4(al[mf][0], al[mf][1], al[mf][2], al[mf][3], tAl + ra);
            }
#pragma unroll
            for (int nf4 = 0; nf4 < 4; nf4++) {
                uint32_t bh[4], bl[4];
                uint32_t rb = (uint32_t)((wn * 64 + nf4 * 16 + b_row) * (MST * 2) +
                                         (ks * 16 + b_k) * 2);
                LDSM4(bh[0], bh[1], bh[2], bh[3], tBh + rb);
                LDSM4(bl[0], bl[1], bl[2], bl[3], tBl + rb);
#pragma unroll
                for (int mf = 0; mf < 2; mf++) {
                    MMA_BF16(acc[mf][nf4 * 2],     ah[mf], bh[0], bh[1]);
                    MMA_BF16(acc[mf][nf4 * 2],     ah[mf], bl[0], bl[1]);
                    MMA_BF16(acc[mf][nf4 * 2],     al[mf], bh[0], bh[1]);
                    MMA_BF16(acc[mf][nf4 * 2 + 1], ah[mf], bh[2], bh[3]);
                    MMA_BF16(acc[mf][nf4 * 2 + 1], ah[mf], bl[2], bl[3]);
                    MMA_BF16(acc[mf][nf4 * 2 + 1], al[mf], bh[2], bh[3]);
                }
            }
        }
        __syncthreads();
    }

    // epilogue: fragment layout m16n8 -> rows lane/4 (+8), cols (lane%4)*2
#pragma unroll
    for (int mf = 0; mf < 2; mf++) {
        int r0 = bm + wm * 32 + mf * 16 + (lane >> 2);
#pragma unroll
        for (int nf = 0; nf < 8; nf++) {
            int cc = bn + wn * 64 + nf * 8 + (lane & 3) * 2;
            *(float2*)&C[(size_t)r0 * DIMC + cc] =
                make_float2(acc[mf][nf][0], acc[mf][nf][1]);
            *(float2*)&C[(size_t)(r0 + 8) * DIMC + cc] =
                make_float2(acc[mf][nf][2], acc[mf][nf][3]);
        }
    }
}

// ---------------- flash attention (R1-passing version) ----------------
__global__ __launch_bounds__(256) void flash_kernel(const float* __restrict__ Qp,
                                                    const float* __restrict__ Kp,
                                                    const float* __restrict__ Vp,
                                                    float* __restrict__ Out) {
    extern __shared__ float smf[];
    float* Qs   = smf;
    float* Ks   = Qs + 64 * FPAD;
    float* Vs   = Ks + 64 * FPAD;
    float* Ss   = Vs + 64 * FPAD;
    float* mrow = Ss + 64 * FPAD;
    float* lrow = mrow + 64;
    float* crow = lrow + 64;

    const int tid = threadIdx.x;
    const int b = blockIdx.z, h = blockIdx.y;
    const int q0 = blockIdx.x * 64;
    const int tx = tid & 15, ty = tid >> 4;
    const int lr = tid >> 2;
    const int lc = (tid & 3) * 16;

    {
        const float* src = Qp + ((size_t)(b * SEQ + q0 + lr)) * DIMC + h * DHD + lc;
        float* dst = Qs + lr * FPAD + lc;
#pragma unroll
        for (int t = 0; t < 4; t++)
            *(float4*)(dst + t * 4) = *(const float4*)(src + t * 4);
    }
    if (tid < 64) { mrow[tid] = -1e38f; lrow[tid] = 0.f; }

    float o[4][4];
#pragma unroll
    for (int i = 0; i < 4; i++)
#pragma unroll
        for (int j = 0; j < 4; j++) o[i][j] = 0.f;

    for (int kt = 0; kt < SEQ / 64; kt++) {
        const int k0 = kt * 64;
        __syncthreads();
        {
            const float* sK = Kp + ((size_t)(b * SEQ + k0 + lr)) * DIMC + h * DHD + lc;
            const float* sV = Vp + ((size_t)(b * SEQ + k0 + lr)) * DIMC + h * DHD + lc;
            float* dK = Ks + lr * FPAD + lc;
            float* dV = Vs + lr * FPAD + lc;
#pragma unroll
            for (int t = 0; t < 4; t++) {
                *(float4*)(dK + t * 4) = *(const float4*)(sK + t * 4);
                *(float4*)(dV + t * 4) = *(const float4*)(sV + t * 4);
            }
        }
        __syncthreads();

        int mk[4];
#pragma unroll
        for (int j = 0; j < 4; j++) mk[j] = g_maskK[b * SEQ + k0 + tx * 4 + j];

        float s[4][4];
#pragma unroll
        for (int i = 0; i < 4; i++)
#pragma unroll
            for (int j = 0; j < 4; j++) s[i][j] = 0.f;

#pragma unroll 4
        for (int d = 0; d < DHD; d += 4) {
            float4 qv[4], kv[4];
#pragma unroll
            for (int i = 0; i < 4; i++) qv[i] = *(const float4*)&Qs[(ty * 4 + i) * FPAD + d];
#pragma unroll
            for (int j = 0; j < 4; j++) kv[j] = *(const float4*)&Ks[(tx * 4 + j) * FPAD + d];
#pragma unroll
            for (int i = 0; i < 4; i++)
#pragma unroll
                for (int j = 0; j < 4; j++) {
                    s[i][j] = fmaf(qv[i].x, kv[j].x, s[i][j]);
                    s[i][j] = fmaf(qv[i].y, kv[j].y, s[i][j]);
                    s[i][j] = fmaf(qv[i].z, kv[j].z, s[i][j]);
                    s[i][j] = fmaf(qv[i].w, kv[j].w, s[i][j]);
                }
        }
#pragma unroll
        for (int i = 0; i < 4; i++)
#pragma unroll
            for (int j = 0; j < 4; j++)
                Ss[(ty * 4 + i) * FPAD + tx * 4 + j] = mk[j] ? -1e38f : s[i][j] * 0.03125f;
        __syncthreads();

        if (tid < 64) {
            float* sr = Ss + tid * FPAD;
            float mo = mrow[tid], mn = mo;
#pragma unroll 8
            for (int j = 0; j < 64; j++) mn = fmaxf(mn, sr[j]);
            float cc = __expf(mo - mn);
            float ls = 0.f;
#pragma unroll 8
            for (int j = 0; j < 64; j++) {
                float p = __expf(sr[j] - mn);
                sr[j] = p;
                ls += p;
            }
            lrow[tid] = lrow[tid] * cc + ls;
            mrow[tid] = mn;
            crow[tid] = cc;
        }
        __syncthreads();

        float cr[4];
#pragma unroll
        for (int i = 0; i < 4; i++) cr[i] = crow[ty * 4 + i];
#pragma unroll
        for (int i = 0; i < 4; i++)
#pragma unroll
            for (int j = 0; j < 4; j++) o[i][j] *= cr[i];

        for (int kk = 0; kk < 64; kk++) {
            float4 v4 = *(const float4*)&Vs[kk * FPAD + tx * 4];
#pragma unroll
            for (int i = 0; i < 4; i++) {
                float p = Ss[(ty * 4 + i) * FPAD + kk];
                o[i][0] = fmaf(p, v4.x, o[i][0]);
                o[i][1] = fmaf(p, v4.y, o[i][1]);
                o[i][2] = fmaf(p, v4.z, o[i][2]);
                o[i][3] = fmaf(p, v4.w, o[i][3]);
            }
        }
    }

#pragma unroll
    for (int i = 0; i < 4; i++) {
        float li = 1.f / lrow[ty * 4 + i];
        float4 v = make_float4(o[i][0] * li, o[i][1] * li, o[i][2] * li, o[i][3] * li);
        *(float4*)&Out[((size_t)(b * SEQ + q0 + ty * 4 + i)) * DIMC + h * DHD + tx * 4] = v;
    }
}

// ---------------- layernorm helpers ----------------
__device__ __forceinline__ void block_reduce2(float& s, float& ss) {
    __shared__ float r1[8], r2[8];
#pragma unroll
    for (int o = 16; o > 0; o >>= 1) {
        s  += __shfl_xor_sync(0xffffffffu, s, o);
        ss += __shfl_xor_sync(0xffffffffu, ss, o);
    }
    int w = threadIdx.x >> 5;
    if ((threadIdx.x & 31) == 0) { r1[w] = s; r2[w] = ss; }
    __syncthreads();
    s = 0.f; ss = 0.f;
#pragma unroll
    for (int i = 0; i < 8; i++) { s += r1[i]; ss += r2[i]; }
}

__global__ __launch_bounds__(256) void ln1_kernel(const float* __restrict__ A,
                                                  const float* __restrict__ Bv,
                                                  const float* __restrict__ gm,
                                                  const float* __restrict__ be,
                                                  float* __restrict__ X) {
    const int row = blockIdx.x;
    float* xo = X + (size_t)row * DIMC;
    if (g_maskQ[row]) {
        for (int i = threadIdx.x; i < DIMC; i += 256) xo[i] = 0.f;
        return;
    }
    const float* a  = A + (size_t)row * DIMC;
    const float* bv = Bv + (size_t)row * DIMC;
    float vals[4];
    float s = 0.f, ss = 0.f;
#pragma unroll
    for (int t = 0; t < 4; t++) {
        int i = threadIdx.x + t * 256;
        float v = a[i] + bv[i];
        vals[t] = v; s += v; ss += v * v;
    }
    block_reduce2(s, ss);
    float mean = s * (1.f / DIMC);
    float var  = ss * (1.f / DIMC) - mean * mean;
    float rstd = rsqrtf(var + 1e-5f);
#pragma unroll
    for (int t = 0; t < 4; t++) {
        int i = threadIdx.x + t * 256;
        xo[i] = (vals[t] - mean) * rstd * gm[i] + be[i];
    }
}

__device__ __forceinline__ float gelu_exact(float x) {
    return 0.5f * x * (1.f + erff(x * 0.70710678118654752f));
}

__global__ __launch_bounds__(256) void final_kernel(const float* __restrict__ X,
                                                    const float* __restrict__ Hx,
                                                    const float* __restrict__ gm,
                                                    const float* __restrict__ be,
                                                    float* __restrict__ out) {
    const int row = blockIdx.x;
    float* o = out + (size_t)row * DIMC;
    if (g_maskQ[row]) {
        for (int i = threadIdx.x; i < DIMC; i += 256) o[i] = 0.f;
        return;
    }
    const float* x = X + (size_t)row * DIMC;
    const float* hv = Hx + (size_t)row * DIMC;
    float vals[4];
    float s = 0.f, ss = 0.f;
#pragma unroll
    for (int t = 0; t < 4; t++) {
        int i = threadIdx.x + t * 256;
        float v = x[i] + gelu_exact(hv[i]);
        vals[t] = v; s += v; ss += v * v;
    }
    block_reduce2(s, ss);
    float mean = s * (1.f / DIMC);
    float var  = ss * (1.f / DIMC) - mean * mean;
    float rstd = rsqrtf(var + 1e-5f);
#pragma unroll
    for (int t = 0; t < 4; t++) {
        int i = threadIdx.x + t * 256;
        o[i] = (vals[t] - mean) * rstd * gm[i] + be[i];
    }
}

// ---------------- launch ----------------
extern "C" void kernel_launch(void* const* d_in, const int* in_sizes, int n_in,
                              void* d_out, int out_size) {
    const float* Q    = (const float*)d_in[0];
    const float* K    = (const float*)d_in[1];
    const float* V    = (const float*)d_in[2];
    const float* Wq   = (const float*)d_in[3];
    const float* Wk   = (const float*)d_in[4];
    const float* Wv   = (const float*)d_in[5];
    const float* Wo   = (const float*)d_in[6];
    const float* ln1g = (const float*)d_in[7];
    const float* ln1b = (const float*)d_in[8];
    const float* ln2g = (const float*)d_in[9];
    const float* ln2b = (const float*)d_in[10];
    const void*  mq   = d_in[11];
    const void*  mk   = d_in[12];
    float* out = (float*)d_out;

    void *pQp, *pKp, *pVp, *pAt, *pX, *pH, *pAh, *pAl, *pWh, *pWl;
    cudaGetSymbolAddress(&pQp, g_Qp);
    cudaGetSymbolAddress(&pKp, g_Kp);
    cudaGetSymbolAddress(&pVp, g_Vp);
    cudaGetSymbolAddress(&pAt, g_attn);
    cudaGetSymbolAddress(&pX,  g_X);
    cudaGetSymbolAddress(&pH,  g_Hb);
    cudaGetSymbolAddress(&pAh, g_Ah);
    cudaGetSymbolAddress(&pAl, g_Al);
    cudaGetSymbolAddress(&pWh, g_Wh);
    cudaGetSymbolAddress(&pWl, g_Wl);
    __nv_bfloat16* Ahp = (__nv_bfloat16*)pAh;
    __nv_bfloat16* Alp = (__nv_bfloat16*)pAl;
    __nv_bfloat16* Whp = (__nv_bfloat16*)pWh;
    __nv_bfloat16* Wlp = (__nv_bfloat16*)pWl;
    const int WSZ = DIMC * DIMC;

    prep_mask_kernel<<<1, 256>>>(mq, mk);

    // weight splits
    const float* Ws[4] = {Wq, Wk, Wv, Wo};
    for (int w = 0; w < 4; w++)
        conv_hilo<<<WSZ / 4 / 256, 256>>>(Ws[w], Whp + (size_t)w * WSZ,
                                          Wlp + (size_t)w * WSZ, WSZ / 4);

    const size_t gsmem = 2 * BUFB;  // 81920 B
    cudaFuncSetAttribute(gemm_mma3, cudaFuncAttributeMaxDynamicSharedMemorySize,
                         (int)gsmem);
    dim3 gg(DIMC / 128, ROWS / 128);  // (8, 32)
    const int ASZ4 = ROWS * DIMC / 4;

    conv_hilo<<<ASZ4 / 256, 256>>>(Q, Ahp, Alp, ASZ4);
    gemm_mma3<<<gg, 256, gsmem>>>(Ahp, Alp, Whp + 0 * (size_t)WSZ,
                                  Wlp + 0 * (size_t)WSZ, (float*)pQp);
    conv_hilo<<<ASZ4 / 256, 256>>>(K, Ahp, Alp, ASZ4);
    gemm_mma3<<<gg, 256, gsmem>>>(Ahp, Alp, Whp + 1 * (size_t)WSZ,
                                  Wlp + 1 * (size_t)WSZ, (float*)pKp);
    conv_hilo<<<ASZ4 / 256, 256>>>(V, Ahp, Alp, ASZ4);
    gemm_mma3<<<gg, 256, gsmem>>>(Ahp, Alp, Whp + 2 * (size_t)WSZ,
                                  Wlp + 2 * (size_t)WSZ, (float*)pVp);

    size_t shmem = (size_t)(4 * 64 * FPAD + 3 * 64) * sizeof(float);
    cudaFuncSetAttribute(flash_kernel, cudaFuncAttributeMaxDynamicSharedMemorySize,
                         (int)shmem);
    flash_kernel<<<dim3(SEQ / 64, NH, BB), 256, shmem>>>(
        (const float*)pQp, (const float*)pKp, (const float*)pVp, (float*)pAt);

    ln1_kernel<<<ROWS, 256>>>((const float*)pQp, (const float*)pAt, ln1g, ln1b,
                              (float*)pX);

    conv_hilo<<<ASZ4 / 256, 256>>>((const float*)pX, Ahp, Alp, ASZ4);
    gemm_mma3<<<gg, 256, gsmem>>>(Ahp, Alp, Whp + 3 * (size_t)WSZ,
                                  Wlp + 3 * (size_t)WSZ, (float*)pH);

    final_kernel<<<ROWS, 256>>>((const float*)pX, (const float*)pH, ln2g, ln2b, out);
}

// round 6
// speedup vs baseline: 3.5478x; 2.5359x over previous
#include <cuda_runtime.h>
#include <cuda_bf16.h>
#include <math.h>
#include <stdint.h>

#define BB   4
#define SEQ  1024
#define DIMC 1024
#define NH   16
#define DHD  64
#define ROWS (BB * SEQ)      // 4096

// ---------------- scratch (device globals: allocation-guard safe) ----------------
__device__ float g_Qp[ROWS * DIMC];
__device__ float g_attn[ROWS * DIMC];
__device__ float g_X[ROWS * DIMC];
__device__ float g_Hb[ROWS * DIMC];
__device__ int   g_maskQ[ROWS];
__device__ float g_maskKF[ROWS];    // 0 or -1e38 addend
// split-bf16 GEMM operands
__device__ __nv_bfloat16 g_Ah[ROWS * DIMC];
__device__ __nv_bfloat16 g_Al[ROWS * DIMC];
__device__ __nv_bfloat16 g_Wh[4][DIMC * DIMC];
__device__ __nv_bfloat16 g_Wl[4][DIMC * DIMC];
// bf16 projected tensors for flash
__device__ __nv_bfloat16 g_Qb[ROWS * DIMC];
__device__ __nv_bfloat16 g_Kb[ROWS * DIMC];
__device__ __nv_bfloat16 g_Vb[ROWS * DIMC];

// ---------------- PTX helpers (base compute_103-safe only) ----------------
__device__ __forceinline__ uint32_t smem_u32(const void* p) {
    uint32_t a;
    asm("{ .reg .u64 t; cvta.to.shared.u64 t, %1; cvt.u32.u64 %0, t; }"
        : "=r"(a) : "l"(p));
    return a;
}

#define CP_ASYNC16(dst, src) \
    asm volatile("cp.async.cg.shared.global [%0], [%1], 16;" \
                 :: "r"(dst), "l"(src) : "memory")
#define CP_COMMIT()  asm volatile("cp.async.commit_group;" ::: "memory")
#define CP_WAIT(n)   asm volatile("cp.async.wait_group %0;" :: "n"(n) : "memory")

#define LDSM4(r0, r1, r2, r3, addr) \
    asm volatile("ldmatrix.sync.aligned.m8n8.x4.shared.b16 {%0,%1,%2,%3}, [%4];" \
                 : "=r"(r0), "=r"(r1), "=r"(r2), "=r"(r3) : "r"(addr))

#define LDSM4T(r0, r1, r2, r3, addr) \
    asm volatile("ldmatrix.sync.aligned.m8n8.x4.trans.shared.b16 {%0,%1,%2,%3}, [%4];" \
                 : "=r"(r0), "=r"(r1), "=r"(r2), "=r"(r3) : "r"(addr))

#define MMA_BF16(d, a, b0, b1) \
    asm volatile("mma.sync.aligned.m16n8k16.row.col.f32.bf16.bf16.f32 " \
                 "{%0,%1,%2,%3}, {%4,%5,%6,%7}, {%8,%9}, {%0,%1,%2,%3};" \
                 : "+f"((d)[0]), "+f"((d)[1]), "+f"((d)[2]), "+f"((d)[3]) \
                 : "r"((a)[0]), "r"((a)[1]), "r"((a)[2]), "r"((a)[3]), \
                   "r"(b0), "r"(b1))

__device__ __forceinline__ uint32_t packbf(float lo, float hi) {
    __nv_bfloat162 v = __floats2bfloat162_rn(lo, hi);  // .x = lo, .y = hi
    return *(uint32_t*)&v;
}

// ---------------- mask canonicalization ----------------
__device__ __forceinline__ int mask_is_bytes(const unsigned int* w) {
    bool wordlike = true;
#pragma unroll
    for (int i = 0; i < 32; i++) {
        unsigned int v = w[i];
        if (v != 0u && v != 1u && v != 0x3F800000u) wordlike = false;
    }
    return wordlike ? 0 : 1;
}

__global__ void prep_mask_kernel(const void* mq, const void* mk) {
    int bq = mask_is_bytes((const unsigned int*)mq);
    int bk = mask_is_bytes((const unsigned int*)mk);
    for (int i = threadIdx.x; i < ROWS; i += blockDim.x) {
        int vq = bq ? (((const unsigned char*)mq)[i] != 0)
                    : (((const unsigned int*)mq)[i] != 0u);
        int vk = bk ? (((const unsigned char*)mk)[i] != 0)
                    : (((const unsigned int*)mk)[i] != 0u);
        g_maskQ[i]  = vq;
        g_maskKF[i] = vk ? -1e38f : 0.f;
    }
}

// ---------------- fp32 -> (bf16 hi, bf16 lo) split ----------------
__global__ __launch_bounds__(256) void conv_hilo(const float* __restrict__ x,
                                                 __nv_bfloat16* __restrict__ hi,
                                                 __nv_bfloat16* __restrict__ lo,
                                                 int n4) {
    int i = blockIdx.x * blockDim.x + threadIdx.x;
    if (i >= n4) return;
    float4 v = ((const float4*)x)[i];
    __nv_bfloat16 h0 = __float2bfloat16(v.x);
    __nv_bfloat16 h1 = __float2bfloat16(v.y);
    __nv_bfloat16 h2 = __float2bfloat16(v.z);
    __nv_bfloat16 h3 = __float2bfloat16(v.w);
    __nv_bfloat16 l0 = __float2bfloat16(v.x - __bfloat162float(h0));
    __nv_bfloat16 l1 = __float2bfloat16(v.y - __bfloat162float(h1));
    __nv_bfloat16 l2 = __float2bfloat16(v.z - __bfloat162float(h2));
    __nv_bfloat16 l3 = __float2bfloat16(v.w - __bfloat162float(h3));
    ((__nv_bfloat162*)hi)[2 * i]     = __nv_bfloat162(h0, h1);
    ((__nv_bfloat162*)hi)[2 * i + 1] = __nv_bfloat162(h2, h3);
    ((__nv_bfloat162*)lo)[2 * i]     = __nv_bfloat162(l0, l1);
    ((__nv_bfloat162*)lo)[2 * i + 1] = __nv_bfloat162(l2, l3);
}

// ---------------- mma.sync split-bf16 GEMM ----------------
// C = A * B^T, 3-pass: Ahi*Bhi + Ahi*Blo + Alo*Bhi.
// CTA 128x128, warp 32x64, K-chunk 32, cp.async double buffer.
#define MST   40
#define TILEB (128 * MST * 2)
#define BUFB  (4 * TILEB)
#define NCH   (DIMC / 32)

__device__ __forceinline__ void gemm_load_chunk(
    uint32_t sbase, const __nv_bfloat16* __restrict__ Ah,
    const __nv_bfloat16* __restrict__ Al, const __nv_bfloat16* __restrict__ Bh,
    const __nv_bfloat16* __restrict__ Bl, int bm, int bn, int k0, int tid) {
#pragma unroll
    for (int h = 0; h < 2; h++) {
        int idx = tid + h * 256;
        int r = idx >> 2, q = idx & 3;
        uint32_t doff = (uint32_t)(r * (MST * 2) + q * 16);
        size_t ga = ((size_t)(bm + r) << 10) + k0 + (q << 3);
        size_t gb = ((size_t)(bn + r) << 10) + k0 + (q << 3);
        CP_ASYNC16(sbase + doff,             Ah + ga);
        CP_ASYNC16(sbase + TILEB + doff,     Al + ga);
        CP_ASYNC16(sbase + 2 * TILEB + doff, Bh + gb);
        CP_ASYNC16(sbase + 3 * TILEB + doff, Bl + gb);
    }
}

__global__ __launch_bounds__(256) void gemm_mma3(
    const __nv_bfloat16* __restrict__ Ah, const __nv_bfloat16* __restrict__ Al,
    const __nv_bfloat16* __restrict__ Bh, const __nv_bfloat16* __restrict__ Bl,
    float* __restrict__ Cf, __nv_bfloat16* __restrict__ Cb) {
    extern __shared__ char sm[];
    const uint32_t base = smem_u32(sm);
    const int tid = threadIdx.x;
    const int bm = blockIdx.y * 128;
    const int bn = blockIdx.x * 128;
    const int warp = tid >> 5, lane = tid & 31;
    const int wm = warp & 3;
    const int wn = warp >> 2;

    float acc[2][8][4];
#pragma unroll
    for (int i = 0; i < 2; i++)
#pragma unroll
        for (int j = 0; j < 8; j++)
#pragma unroll
            for (int k = 0; k < 4; k++) acc[i][j][k] = 0.f;

    gemm_load_chunk(base, Ah, Al, Bh, Bl, bm, bn, 0, tid);
    CP_COMMIT();

    const int a_row = (lane & 15);
    const int a_k   = (lane >> 4) * 8;
    const int b_row = (lane & 7) + ((lane >> 4) << 3);
    const int b_k   = ((lane >> 3) & 1) * 8;

    for (int c = 0; c < NCH; c++) {
        if (c + 1 < NCH) {
            gemm_load_chunk(base + ((c + 1) & 1) * BUFB, Ah, Al, Bh, Bl,
                            bm, bn, (c + 1) * 32, tid);
            CP_COMMIT();
            CP_WAIT(1);
        } else {
            CP_WAIT(0);
        }
        __syncthreads();

        const uint32_t bu = base + (c & 1) * BUFB;
        const uint32_t tAh = bu;
        const uint32_t tAl = bu + TILEB;
        const uint32_t tBh = bu + 2 * TILEB;
        const uint32_t tBl = bu + 3 * TILEB;

#pragma unroll
        for (int ks = 0; ks < 2; ks++) {
            uint32_t ah[2][4], al[2][4];
            const int kk = ks * 16 + a_k;
#pragma unroll
            for (int mf = 0; mf < 2; mf++) {
                uint32_t ra = (uint32_t)((wm * 32 + mf * 16 + a_row) * (MST * 2) + kk * 2);
                LDSM4(ah[mf][0], ah[mf][1], ah[mf][2], ah[mf][3], tAh + ra);
                LDSM4(al[mf][0], al[mf][1], al[mf][2], al[mf][3], tAl + ra);
            }
#pragma unroll
            for (int nf4 = 0; nf4 < 4; nf4++) {
                uint32_t bh[4], bl[4];
                uint32_t rb = (uint32_t)((wn * 64 + nf4 * 16 + b_row) * (MST * 2) +
                                         (ks * 16 + b_k) * 2);
                LDSM4(bh[0], bh[1], bh[2], bh[3], tBh + rb);
                LDSM4(bl[0], bl[1], bl[2], bl[3], tBl + rb);
#pragma unroll
                for (int mf = 0; mf < 2; mf++) {
                    MMA_BF16(acc[mf][nf4 * 2],     ah[mf], bh[0], bh[1]);
                    MMA_BF16(acc[mf][nf4 * 2],     ah[mf], bl[0], bl[1]);
                    MMA_BF16(acc[mf][nf4 * 2],     al[mf], bh[0], bh[1]);
                    MMA_BF16(acc[mf][nf4 * 2 + 1], ah[mf], bh[2], bh[3]);
                    MMA_BF16(acc[mf][nf4 * 2 + 1], ah[mf], bl[2], bl[3]);
                    MMA_BF16(acc[mf][nf4 * 2 + 1], al[mf], bh[2], bh[3]);
                }
            }
        }
        __syncthreads();
    }

#pragma unroll
    for (int mf = 0; mf < 2; mf++) {
        int r0 = bm + wm * 32 + mf * 16 + (lane >> 2);
#pragma unroll
        for (int nf = 0; nf < 8; nf++) {
            int cc = bn + wn * 64 + nf * 8 + (lane & 3) * 2;
            if (Cf) {
                *(float2*)&Cf[(size_t)r0 * DIMC + cc] =
                    make_float2(acc[mf][nf][0], acc[mf][nf][1]);
                *(float2*)&Cf[(size_t)(r0 + 8) * DIMC + cc] =
                    make_float2(acc[mf][nf][2], acc[mf][nf][3]);
            }
            if (Cb) {
                *(uint32_t*)&Cb[(size_t)r0 * DIMC + cc] =
                    packbf(acc[mf][nf][0], acc[mf][nf][1]);
                *(uint32_t*)&Cb[(size_t)(r0 + 8) * DIMC + cc] =
                    packbf(acc[mf][nf][2], acc[mf][nf][3]);
            }
        }
    }
}

// ---------------- tensor-core flash attention ----------------
// CTA: 128 q-rows x one (b,h). 8 warps, warp handles m16. K-tiles of 128 keys.
// smem: Q tile (stride 144B) + 2 stages of {K, V, maskf}.
#define FKST   144                         // bytes per 64-bf16 row (72 bf16)
#define FQTB   (128 * FKST)                // 18432
#define FSTGB  (2 * FQTB + 512)            // K + V + 128 mask floats = 37376
#define FSCL   0.03125f

__device__ __forceinline__ void flash_load_stage(
    uint32_t sb, const __nv_bfloat16* __restrict__ Kb,
    const __nv_bfloat16* __restrict__ Vb, const float* __restrict__ mKF,
    int bz, int h, int k0, int tid) {
#pragma unroll
    for (int i = 0; i < 4; i++) {
        int idx = tid + i * 256;
        int r = idx >> 3, cq = idx & 7;
        size_t go = ((size_t)(bz * SEQ + k0 + r)) * DIMC + h * DHD + cq * 8;
        uint32_t doff = (uint32_t)(r * FKST + cq * 16);
        CP_ASYNC16(sb + doff,        Kb + go);
        CP_ASYNC16(sb + FQTB + doff, Vb + go);
    }
    if (tid < 32)
        CP_ASYNC16(sb + 2 * FQTB + tid * 16, mKF + bz * SEQ + k0 + tid * 4);
}

__global__ __launch_bounds__(256) void flash_mma(
    const __nv_bfloat16* __restrict__ Qb, const __nv_bfloat16* __restrict__ Kb,
    const __nv_bfloat16* __restrict__ Vb, float* __restrict__ Out) {
    extern __shared__ char sm[];
    const uint32_t qbase = smem_u32(sm);
    const uint32_t sbase = qbase + FQTB;
    const float* mKF = g_maskKF;

    const int tid = threadIdx.x;
    const int bz = blockIdx.z, h = blockIdx.y;
    const int q0 = blockIdx.x * 128;
    const int lane = tid & 31, wq = tid >> 5;

    // load Q tile (group 0)
#pragma unroll
    for (int i = 0; i < 4; i++) {
        int idx = tid + i * 256;
        int r = idx >> 3, cq = idx & 7;
        CP_ASYNC16(qbase + r * FKST + cq * 16,
                   Qb + ((size_t)(bz * SEQ + q0 + r)) * DIMC + h * DHD + cq * 8);
    }
    CP_COMMIT();
    flash_load_stage(sbase, Kb, Vb, mKF, bz, h, 0, tid);
    CP_COMMIT();

    const int a_row = (lane & 15);
    const int a_c16 = (lane >> 4) * 16;          // bytes
    const int b_row = (lane & 7) + ((lane >> 4) << 3);
    const int b_c16 = ((lane >> 3) & 1) * 16;    // bytes

    float m0 = -1e38f, m1 = -1e38f, l0 = 0.f, l1 = 0.f;
    float o[8][4];
#pragma unroll
    for (int i = 0; i < 8; i++)
#pragma unroll
        for (int j = 0; j < 4; j++) o[i][j] = 0.f;
    uint32_t qa[4][4];

    for (int c = 0; c < SEQ / 128; c++) {
        if (c + 1 < SEQ / 128) {
            flash_load_stage(sbase + ((c + 1) & 1) * FSTGB, Kb, Vb, mKF,
                             bz, h, (c + 1) * 128, tid);
            CP_COMMIT();
            CP_WAIT(1);
        } else {
            CP_WAIT(0);
        }
        __syncthreads();

        if (c == 0) {
#pragma unroll
            for (int ks = 0; ks < 4; ks++)
                LDSM4(qa[ks][0], qa[ks][1], qa[ks][2], qa[ks][3],
                      qbase + (wq * 16 + a_row) * FKST + ks * 32 + a_c16);
        }

        const uint32_t Kt = sbase + (c & 1) * FSTGB;
        const uint32_t Vt = Kt + FQTB;
        const uint32_t Mq = Kt + 2 * FQTB;

        // S = Q K^T fragments
        float s[16][4];
#pragma unroll
        for (int i = 0; i < 16; i++)
#pragma unroll
            for (int j = 0; j < 4; j++) s[i][j] = 0.f;

#pragma unroll
        for (int kb = 0; kb < 8; kb++) {
#pragma unroll
            for (int ks = 0; ks < 4; ks++) {
                uint32_t b0, b1, b2, b3;
                LDSM4(b0, b1, b2, b3,
                      Kt + (kb * 16 + b_row) * FKST + ks * 32 + b_c16);
                MMA_BF16(s[2 * kb],     qa[ks], b0, b1);
                MMA_BF16(s[2 * kb + 1], qa[ks], b2, b3);
            }
        }

        // key-mask addend (unscaled logits; masked -> -1e38)
#pragma unroll
        for (int nf = 0; nf < 16; nf++) {
            float2 ma;
            asm volatile("ld.shared.v2.f32 {%0,%1}, [%2];"
                         : "=f"(ma.x), "=f"(ma.y)
                         : "r"(Mq + (uint32_t)(nf * 32 + (lane & 3) * 8)));
            s[nf][0] += ma.x; s[nf][1] += ma.y;
            s[nf][2] += ma.x; s[nf][3] += ma.y;
        }

        // row max (rows r=lane>>2 and r+8; reduce over 4-lane groups)
        float mx0 = m0, mx1 = m1;
#pragma unroll
        for (int nf = 0; nf < 16; nf++) {
            mx0 = fmaxf(mx0, fmaxf(s[nf][0], s[nf][1]));
            mx1 = fmaxf(mx1, fmaxf(s[nf][2], s[nf][3]));
        }
#pragma unroll
        for (int off = 1; off <= 2; off <<= 1) {
            mx0 = fmaxf(mx0, __shfl_xor_sync(0xffffffffu, mx0, off));
            mx1 = fmaxf(mx1, __shfl_xor_sync(0xffffffffu, mx1, off));
        }
        const float c0 = __expf((m0 - mx0) * FSCL);
        const float c1 = __expf((m1 - mx1) * FSCL);
        m0 = mx0; m1 = mx1;
        l0 *= c0; l1 *= c1;
#pragma unroll
        for (int nf = 0; nf < 8; nf++) {
            o[nf][0] *= c0; o[nf][1] *= c0;
            o[nf][2] *= c1; o[nf][3] *= c1;
        }

        const float mk0 = mx0 * FSCL, mk1 = mx1 * FSCL;
        float ls0 = 0.f, ls1 = 0.f;
#pragma unroll
        for (int nf = 0; nf < 16; nf++) {
            s[nf][0] = __expf(fmaf(s[nf][0], FSCL, -mk0));
            s[nf][1] = __expf(fmaf(s[nf][1], FSCL, -mk0));
            s[nf][2] = __expf(fmaf(s[nf][2], FSCL, -mk1));
            s[nf][3] = __expf(fmaf(s[nf][3], FSCL, -mk1));
            ls0 += s[nf][0] + s[nf][1];
            ls1 += s[nf][2] + s[nf][3];
        }
#pragma unroll
        for (int off = 1; off <= 2; off <<= 1) {
            ls0 += __shfl_xor_sync(0xffffffffu, ls0, off);
            ls1 += __shfl_xor_sync(0xffffffffu, ls1, off);
        }
        l0 += ls0; l1 += ls1;

        // O += P V
#pragma unroll
        for (int kv = 0; kv < 8; kv++) {
            uint32_t pa[4];
            pa[0] = packbf(s[2 * kv][0],     s[2 * kv][1]);
            pa[1] = packbf(s[2 * kv][2],     s[2 * kv][3]);
            pa[2] = packbf(s[2 * kv + 1][0], s[2 * kv + 1][1]);
            pa[3] = packbf(s[2 * kv + 1][2], s[2 * kv + 1][3]);
#pragma unroll
            for (int dp = 0; dp < 4; dp++) {
                uint32_t v0, v1, v2, v3;
                LDSM4T(v0, v1, v2, v3,
                       Vt + (kv * 16 + a_row) * FKST + dp * 32 + a_c16);
                MMA_BF16(o[2 * dp],     pa, v0, v1);
                MMA_BF16(o[2 * dp + 1], pa, v2, v3);
            }
        }
        __syncthreads();
    }

    const float inv0 = 1.f / l0, inv1 = 1.f / l1;
    const int row0 = bz * SEQ + q0 + wq * 16 + (lane >> 2);
#pragma unroll
    for (int nf = 0; nf < 8; nf++) {
        int cc = h * DHD + nf * 8 + (lane & 3) * 2;
        *(float2*)&Out[(size_t)row0 * DIMC + cc] =
            make_float2(o[nf][0] * inv0, o[nf][1] * inv0);
        *(float2*)&Out[(size_t)(row0 + 8) * DIMC + cc] =
            make_float2(o[nf][2] * inv1, o[nf][3] * inv1);
    }
}

// ---------------- layernorm helpers ----------------
__device__ __forceinline__ void block_reduce2(float& s, float& ss) {
    __shared__ float r1[8], r2[8];
#pragma unroll
    for (int o = 16; o > 0; o >>= 1) {
        s  += __shfl_xor_sync(0xffffffffu, s, o);
        ss += __shfl_xor_sync(0xffffffffu, ss, o);
    }
    int w = threadIdx.x >> 5;
    if ((threadIdx.x & 31) == 0) { r1[w] = s; r2[w] = ss; }
    __syncthreads();
    s = 0.f; ss = 0.f;
#pragma unroll
    for (int i = 0; i < 8; i++) { s += r1[i]; ss += r2[i]; }
}

// LN1: X = LN(Qp + attn) (zeroed on masked rows); also emits hi/lo split of X.
__global__ __launch_bounds__(256) void ln1_kernel(const float* __restrict__ A,
                                                  const float* __restrict__ Bv,
                                                  const float* __restrict__ gm,
                                                  const float* __restrict__ be,
                                                  float* __restrict__ X,
                                                  __nv_bfloat16* __restrict__ Xh,
                                                  __nv_bfloat16* __restrict__ Xl) {
    const int row = blockIdx.x;
    float* xo = X + (size_t)row * DIMC;
    __nv_bfloat16* xh = Xh + (size_t)row * DIMC;
    __nv_bfloat16* xl = Xl + (size_t)row * DIMC;
    if (g_maskQ[row]) {
        for (int i = threadIdx.x; i < DIMC; i += 256) {
            xo[i] = 0.f;
            xh[i] = __float2bfloat16(0.f);
            xl[i] = __float2bfloat16(0.f);
        }
        return;
    }
    const float* a  = A + (size_t)row * DIMC;
    const float* bv = Bv + (size_t)row * DIMC;
    float vals[4];
    float s = 0.f, ss = 0.f;
#pragma unroll
    for (int t = 0; t < 4; t++) {
        int i = threadIdx.x + t * 256;
        float v = a[i] + bv[i];
        vals[t] = v; s += v; ss += v * v;
    }
    block_reduce2(s, ss);
    float mean = s * (1.f / DIMC);
    float var  = ss * (1.f / DIMC) - mean * mean;
    float rstd = rsqrtf(var + 1e-5f);
#pragma unroll
    for (int t = 0; t < 4; t++) {
        int i = threadIdx.x + t * 256;
        float v = (vals[t] - mean) * rstd * gm[i] + be[i];
        xo[i] = v;
        __nv_bfloat16 hh = __float2bfloat16(v);
        xh[i] = hh;
        xl[i] = __float2bfloat16(v - __bfloat162float(hh));
    }
}

__device__ __forceinline__ float gelu_exact(float x) {
    return 0.5f * x * (1.f + erff(x * 0.70710678118654752f));
}

__global__ __launch_bounds__(256) void final_kernel(const float* __restrict__ X,
                                                    const float* __restrict__ Hx,
                                                    const float* __restrict__ gm,
                                                    const float* __restrict__ be,
                                                    float* __restrict__ out) {
    const int row = blockIdx.x;
    float* o = out + (size_t)row * DIMC;
    if (g_maskQ[row]) {
        for (int i = threadIdx.x; i < DIMC; i += 256) o[i] = 0.f;
        return;
    }
    const float* x = X + (size_t)row * DIMC;
    const float* hv = Hx + (size_t)row * DIMC;
    float vals[4];
    float s = 0.f, ss = 0.f;
#pragma unroll
    for (int t = 0; t < 4; t++) {
        int i = threadIdx.x + t * 256;
        float v = x[i] + gelu_exact(hv[i]);
        vals[t] = v; s += v; ss += v * v;
    }
    block_reduce2(s, ss);
    float mean = s * (1.f / DIMC);
    float var  = ss * (1.f / DIMC) - mean * mean;
    float rstd = rsqrtf(var + 1e-5f);
#pragma unroll
    for (int t = 0; t < 4; t++) {
        int i = threadIdx.x + t * 256;
        o[i] = (vals[t] - mean) * rstd * gm[i] + be[i];
    }
}

// ---------------- launch ----------------
extern "C" void kernel_launch(void* const* d_in, const int* in_sizes, int n_in,
                              void* d_out, int out_size) {
    const float* Q    = (const float*)d_in[0];
    const float* K    = (const float*)d_in[1];
    const float* V    = (const float*)d_in[2];
    const float* Wq   = (const float*)d_in[3];
    const float* Wk   = (const float*)d_in[4];
    const float* Wv   = (const float*)d_in[5];
    const float* Wo   = (const float*)d_in[6];
    const float* ln1g = (const float*)d_in[7];
    const float* ln1b = (const float*)d_in[8];
    const float* ln2g = (const float*)d_in[9];
    const float* ln2b = (const float*)d_in[10];
    const void*  mq   = d_in[11];
    const void*  mk   = d_in[12];
    float* out = (float*)d_out;

    void *pQp, *pAt, *pX, *pH, *pAh, *pAl, *pWh, *pWl, *pQb, *pKb, *pVb;
    cudaGetSymbolAddress(&pQp, g_Qp);
    cudaGetSymbolAddress(&pAt, g_attn);
    cudaGetSymbolAddress(&pX,  g_X);
    cudaGetSymbolAddress(&pH,  g_Hb);
    cudaGetSymbolAddress(&pAh, g_Ah);
    cudaGetSymbolAddress(&pAl, g_Al);
    cudaGetSymbolAddress(&pWh, g_Wh);
    cudaGetSymbolAddress(&pWl, g_Wl);
    cudaGetSymbolAddress(&pQb, g_Qb);
    cudaGetSymbolAddress(&pKb, g_Kb);
    cudaGetSymbolAddress(&pVb, g_Vb);
    __nv_bfloat16* Ahp = (__nv_bfloat16*)pAh;
    __nv_bfloat16* Alp = (__nv_bfloat16*)pAl;
    __nv_bfloat16* Whp = (__nv_bfloat16*)pWh;
    __nv_bfloat16* Wlp = (__nv_bfloat16*)pWl;
    const int WSZ = DIMC * DIMC;

    prep_mask_kernel<<<1, 256>>>(mq, mk);

    const float* Ws[4] = {Wq, Wk, Wv, Wo};
    for (int w = 0; w < 4; w++)
        conv_hilo<<<WSZ / 4 / 256, 256>>>(Ws[w], Whp + (size_t)w * WSZ,
                                          Wlp + (size_t)w * WSZ, WSZ / 4);

    const size_t gsmem = 2 * BUFB;  // 81920 B
    cudaFuncSetAttribute(gemm_mma3, cudaFuncAttributeMaxDynamicSharedMemorySize,
                         (int)gsmem);
    dim3 gg(DIMC / 128, ROWS / 128);  // (8, 32)
    const int ASZ4 = ROWS * DIMC / 4;

    conv_hilo<<<ASZ4 / 256, 256>>>(Q, Ahp, Alp, ASZ4);
    gemm_mma3<<<gg, 256, gsmem>>>(Ahp, Alp, Whp + 0 * (size_t)WSZ,
                                  Wlp + 0 * (size_t)WSZ, (float*)pQp,
                                  (__nv_bfloat16*)pQb);
    conv_hilo<<<ASZ4 / 256, 256>>>(K, Ahp, Alp, ASZ4);
    gemm_mma3<<<gg, 256, gsmem>>>(Ahp, Alp, Whp + 1 * (size_t)WSZ,
                                  Wlp + 1 * (size_t)WSZ, (float*)nullptr,
                                  (__nv_bfloat16*)pKb);
    conv_hilo<<<ASZ4 / 256, 256>>>(V, Ahp, Alp, ASZ4);
    gemm_mma3<<<gg, 256, gsmem>>>(Ahp, Alp, Whp + 2 * (size_t)WSZ,
                                  Wlp + 2 * (size_t)WSZ, (float*)nullptr,
                                  (__nv_bfloat16*)pVb);

    const size_t fsmem = FQTB + 2 * FSTGB;  // 93184 B
    cudaFuncSetAttribute(flash_mma, cudaFuncAttributeMaxDynamicSharedMemorySize,
                         (int)fsmem);
    flash_mma<<<dim3(SEQ / 128, NH, BB), 256, fsmem>>>(
        (const __nv_bfloat16*)pQb, (const __nv_bfloat16*)pKb,
        (const __nv_bfloat16*)pVb, (float*)pAt);

    ln1_kernel<<<ROWS, 256>>>((const float*)pQp, (const float*)pAt, ln1g, ln1b,
                              (float*)pX, Ahp, Alp);

    gemm_mma3<<<gg, 256, gsmem>>>(Ahp, Alp, Whp + 3 * (size_t)WSZ,
                                  Wlp + 3 * (size_t)WSZ, (float*)pH,
                                  (__nv_bfloat16*)nullptr);

    final_kernel<<<ROWS, 256>>>((const float*)pX, (const float*)pH, ln2g, ln2b, out);
}

// round 7
// speedup vs baseline: 4.3360x; 1.2222x over previous
#include <cuda_runtime.h>
#include <cuda_bf16.h>
#include <math.h>
#include <stdint.h>

#define BB   4
#define SEQ  1024
#define DIMC 1024
#define NH   16
#define DHD  64
#define ROWS (BB * SEQ)      // 4096

// ---------------- scratch (device globals: allocation-guard safe) ----------------
__device__ float g_Qp[ROWS * DIMC];
__device__ float g_attn[ROWS * DIMC];
__device__ float g_X[ROWS * DIMC];
__device__ float g_Hb[ROWS * DIMC];
__device__ int   g_maskQ[ROWS];
__device__ float g_maskKF[ROWS];    // 0 or -1e38 addend
// split-bf16 GEMM operands
__device__ __nv_bfloat16 g_Ah[ROWS * DIMC];
__device__ __nv_bfloat16 g_Al[ROWS * DIMC];
__device__ __nv_bfloat16 g_Ih[ROWS * DIMC];    // K input hi
__device__ __nv_bfloat16 g_Ih2[ROWS * DIMC];   // V input hi
__device__ __nv_bfloat16 g_Wh[4][DIMC * DIMC];
__device__ __nv_bfloat16 g_Wl[4][DIMC * DIMC];
// bf16 projected tensors for flash
__device__ __nv_bfloat16 g_Qb[ROWS * DIMC];
__device__ __nv_bfloat16 g_Kb[ROWS * DIMC];
__device__ __nv_bfloat16 g_Vb[ROWS * DIMC];

// ---------------- PTX helpers (base compute_103-safe only) ----------------
__device__ __forceinline__ uint32_t smem_u32(const void* p) {
    uint32_t a;
    asm("{ .reg .u64 t; cvta.to.shared.u64 t, %1; cvt.u32.u64 %0, t; }"
        : "=r"(a) : "l"(p));
    return a;
}

#define CP_ASYNC16(dst, src) \
    asm volatile("cp.async.cg.shared.global [%0], [%1], 16;" \
                 :: "r"(dst), "l"(src) : "memory")
#define CP_COMMIT()  asm volatile("cp.async.commit_group;" ::: "memory")
#define CP_WAIT(n)   asm volatile("cp.async.wait_group %0;" :: "n"(n) : "memory")

#define LDSM4(r0, r1, r2, r3, addr) \
    asm volatile("ldmatrix.sync.aligned.m8n8.x4.shared.b16 {%0,%1,%2,%3}, [%4];" \
                 : "=r"(r0), "=r"(r1), "=r"(r2), "=r"(r3) : "r"(addr))

#define LDSM4T(r0, r1, r2, r3, addr) \
    asm volatile("ldmatrix.sync.aligned.m8n8.x4.trans.shared.b16 {%0,%1,%2,%3}, [%4];" \
                 : "=r"(r0), "=r"(r1), "=r"(r2), "=r"(r3) : "r"(addr))

#define MMA_BF16(d, a, b0, b1) \
    asm volatile("mma.sync.aligned.m16n8k16.row.col.f32.bf16.bf16.f32 " \
                 "{%0,%1,%2,%3}, {%4,%5,%6,%7}, {%8,%9}, {%0,%1,%2,%3};" \
                 : "+f"((d)[0]), "+f"((d)[1]), "+f"((d)[2]), "+f"((d)[3]) \
                 : "r"((a)[0]), "r"((a)[1]), "r"((a)[2]), "r"((a)[3]), \
                   "r"(b0), "r"(b1))

__device__ __forceinline__ uint32_t packbf(float lo, float hi) {
    __nv_bfloat162 v = __floats2bfloat162_rn(lo, hi);
    return *(uint32_t*)&v;
}

// ---------------- mask canonicalization ----------------
__device__ __forceinline__ int mask_is_bytes(const unsigned int* w) {
    bool wordlike = true;
#pragma unroll
    for (int i = 0; i < 32; i++) {
        unsigned int v = w[i];
        if (v != 0u && v != 1u && v != 0x3F800000u) wordlike = false;
    }
    return wordlike ? 0 : 1;
}

__global__ void prep_mask_kernel(const void* mq, const void* mk) {
    int bq = mask_is_bytes((const unsigned int*)mq);
    int bk = mask_is_bytes((const unsigned int*)mk);
    for (int i = threadIdx.x; i < ROWS; i += blockDim.x) {
        int vq = bq ? (((const unsigned char*)mq)[i] != 0)
                    : (((const unsigned int*)mq)[i] != 0u);
        int vk = bk ? (((const unsigned char*)mk)[i] != 0)
                    : (((const unsigned int*)mk)[i] != 0u);
        g_maskQ[i]  = vq;
        g_maskKF[i] = vk ? -1e38f : 0.f;
    }
}

// ---------------- batched fp32 -> bf16 (hi [, lo]) conversion ----------------
struct ConvJob { const float* src; __nv_bfloat16* hi; __nv_bfloat16* lo; int n4; };
struct ConvJobs4 { ConvJob j[4]; };

__global__ __launch_bounds__(256) void conv_batch(ConvJobs4 jobs) {
    const ConvJob jb = jobs.j[blockIdx.z];
    int i = blockIdx.x * 256 + threadIdx.x;
    if (i >= jb.n4) return;
    float4 v = ((const float4*)jb.src)[i];
    __nv_bfloat16 h0 = __float2bfloat16(v.x);
    __nv_bfloat16 h1 = __float2bfloat16(v.y);
    __nv_bfloat16 h2 = __float2bfloat16(v.z);
    __nv_bfloat16 h3 = __float2bfloat16(v.w);
    ((__nv_bfloat162*)jb.hi)[2 * i]     = __nv_bfloat162(h0, h1);
    ((__nv_bfloat162*)jb.hi)[2 * i + 1] = __nv_bfloat162(h2, h3);
    if (jb.lo) {
        __nv_bfloat16 l0 = __float2bfloat16(v.x - __bfloat162float(h0));
        __nv_bfloat16 l1 = __float2bfloat16(v.y - __bfloat162float(h1));
        __nv_bfloat16 l2 = __float2bfloat16(v.z - __bfloat162float(h2));
        __nv_bfloat16 l3 = __float2bfloat16(v.w - __bfloat162float(h3));
        ((__nv_bfloat162*)jb.lo)[2 * i]     = __nv_bfloat162(l0, l1);
        ((__nv_bfloat162*)jb.lo)[2 * i + 1] = __nv_bfloat162(l2, l3);
    }
}

// ---------------- 3-pass split-bf16 GEMM (Q and Wo projections) ----------------
// C = A * B^T: Ahi*Bhi + Ahi*Blo + Alo*Bhi. CTA 128x128, warp 32x64.
// K-chunk 32, 3-stage cp.async, ONE barrier per chunk.
#define MST   40
#define TILEB (128 * MST * 2)        // 10240
#define BUFB  (4 * TILEB)            // 40960 per stage
#define NCH   (DIMC / 32)            // 32

__device__ __forceinline__ void g3_load(
    uint32_t sbase, const __nv_bfloat16* __restrict__ Ah,
    const __nv_bfloat16* __restrict__ Al, const __nv_bfloat16* __restrict__ Bh,
    const __nv_bfloat16* __restrict__ Bl, int bm, int bn, int k0, int tid) {
#pragma unroll
    for (int h = 0; h < 2; h++) {
        int idx = tid + h * 256;
        int r = idx >> 2, q = idx & 3;
        uint32_t doff = (uint32_t)(r * (MST * 2) + q * 16);
        size_t ga = ((size_t)(bm + r) << 10) + k0 + (q << 3);
        size_t gb = ((size_t)(bn + r) << 10) + k0 + (q << 3);
        CP_ASYNC16(sbase + doff,             Ah + ga);
        CP_ASYNC16(sbase + TILEB + doff,     Al + ga);
        CP_ASYNC16(sbase + 2 * TILEB + doff, Bh + gb);
        CP_ASYNC16(sbase + 3 * TILEB + doff, Bl + gb);
    }
}

__global__ __launch_bounds__(256) void gemm_mma3(
    const __nv_bfloat16* __restrict__ Ah, const __nv_bfloat16* __restrict__ Al,
    const __nv_bfloat16* __restrict__ Bh, const __nv_bfloat16* __restrict__ Bl,
    float* __restrict__ Cf, __nv_bfloat16* __restrict__ Cb) {
    extern __shared__ char sm[];
    const uint32_t base = smem_u32(sm);
    const int tid = threadIdx.x;
    const int bm = blockIdx.y * 128;
    const int bn = blockIdx.x * 128;
    const int warp = tid >> 5, lane = tid & 31;
    const int wm = warp & 3;
    const int wn = warp >> 2;

    float acc[2][8][4];
#pragma unroll
    for (int i = 0; i < 2; i++)
#pragma unroll
        for (int j = 0; j < 8; j++)
#pragma unroll
            for (int k = 0; k < 4; k++) acc[i][j][k] = 0.f;

    g3_load(base, Ah, Al, Bh, Bl, bm, bn, 0, tid);
    CP_COMMIT();
    g3_load(base + BUFB, Ah, Al, Bh, Bl, bm, bn, 32, tid);
    CP_COMMIT();
    CP_WAIT(1);
    __syncthreads();

    const int a_row = (lane & 15);
    const int a_k   = (lane >> 4) * 8;
    const int b_row = (lane & 7) + ((lane >> 4) << 3);
    const int b_k   = ((lane >> 3) & 1) * 8;

    for (int c = 0; c < NCH; c++) {
        if (c + 2 < NCH) {
            g3_load(base + ((c + 2) % 3) * BUFB, Ah, Al, Bh, Bl,
                    bm, bn, (c + 2) * 32, tid);
            CP_COMMIT();
        }

        const uint32_t bu = base + (c % 3) * BUFB;
        const uint32_t tAh = bu;
        const uint32_t tAl = bu + TILEB;
        const uint32_t tBh = bu + 2 * TILEB;
        const uint32_t tBl = bu + 3 * TILEB;

#pragma unroll
        for (int ks = 0; ks < 2; ks++) {
            uint32_t ah[2][4], al[2][4];
            const int kk = ks * 16 + a_k;
#pragma unroll
            for (int mf = 0; mf < 2; mf++) {
                uint32_t ra = (uint32_t)((wm * 32 + mf * 16 + a_row) * (MST * 2) + kk * 2);
                LDSM4(ah[mf][0], ah[mf][1], ah[mf][2], ah[mf][3], tAh + ra);
                LDSM4(al[mf][0], al[mf][1], al[mf][2], al[mf][3], tAl + ra);
            }
#pragma unroll
            for (int nf4 = 0; nf4 < 4; nf4++) {
                uint32_t bh[4], bl[4];
                uint32_t rb = (uint32_t)((wn * 64 + nf4 * 16 + b_row) * (MST * 2) +
                                         (ks * 16 + b_k) * 2);
                LDSM4(bh[0], bh[1], bh[2], bh[3], tBh + rb);
                LDSM4(bl[0], bl[1], bl[2], bl[3], tBl + rb);
#pragma unroll
                for (int mf = 0; mf < 2; mf++) {
                    MMA_BF16(acc[mf][nf4 * 2],     ah[mf], bh[0], bh[1]);
                    MMA_BF16(acc[mf][nf4 * 2],     ah[mf], bl[0], bl[1]);
                    MMA_BF16(acc[mf][nf4 * 2],     al[mf], bh[0], bh[1]);
                    MMA_BF16(acc[mf][nf4 * 2 + 1], ah[mf], bh[2], bh[3]);
                    MMA_BF16(acc[mf][nf4 * 2 + 1], ah[mf], bl[2], bl[3]);
                    MMA_BF16(acc[mf][nf4 * 2 + 1], al[mf], bh[2], bh[3]);
                }
            }
        }

        if (c + 2 < NCH)      { CP_WAIT(1); }
        else if (c + 1 < NCH) { CP_WAIT(0); }
        __syncthreads();
    }

#pragma unroll
    for (int mf = 0; mf < 2; mf++) {
        int r0 = bm + wm * 32 + mf * 16 + (lane >> 2);
#pragma unroll
        for (int nf = 0; nf < 8; nf++) {
            int cc = bn + wn * 64 + nf * 8 + (lane & 3) * 2;
            if (Cf) {
                *(float2*)&Cf[(size_t)r0 * DIMC + cc] =
                    make_float2(acc[mf][nf][0], acc[mf][nf][1]);
                *(float2*)&Cf[(size_t)(r0 + 8) * DIMC + cc] =
                    make_float2(acc[mf][nf][2], acc[mf][nf][3]);
            }
            if (Cb) {
                *(uint32_t*)&Cb[(size_t)r0 * DIMC + cc] =
                    packbf(acc[mf][nf][0], acc[mf][nf][1]);
                *(uint32_t*)&Cb[(size_t)(r0 + 8) * DIMC + cc] =
                    packbf(acc[mf][nf][2], acc[mf][nf][3]);
            }
        }
    }
}

// ---------------- 1-pass bf16 GEMM (K and V projections, batched) ----------------
// Cb = bf16(Ah * Bh^T). K-chunk 64, 3-stage, one barrier per chunk. z selects job.
#define T1ST  72                      // halves per row (144 B)
#define T1B   (128 * T1ST * 2)        // 18432
#define S1B   (2 * T1B)               // 36864 per stage
#define NCH1  (DIMC / 64)             // 16

__device__ __forceinline__ void g1_load(
    uint32_t sbase, const __nv_bfloat16* __restrict__ A,
    const __nv_bfloat16* __restrict__ B, int bm, int bn, int k0, int tid) {
#pragma unroll
    for (int i = 0; i < 4; i++) {
        int idx = tid + i * 256;
        int r = idx >> 3, q = idx & 7;
        uint32_t doff = (uint32_t)(r * (T1ST * 2) + q * 16);
        CP_ASYNC16(sbase + doff,       A + (((size_t)(bm + r)) << 10) + k0 + (q << 3));
        CP_ASYNC16(sbase + T1B + doff, B + (((size_t)(bn + r)) << 10) + k0 + (q << 3));
    }
}

__global__ __launch_bounds__(256) void gemm_mma1(
    const __nv_bfloat16* __restrict__ A0, const __nv_bfloat16* __restrict__ B0,
    __nv_bfloat16* __restrict__ C0,
    const __nv_bfloat16* __restrict__ A1, const __nv_bfloat16* __restrict__ B1,
    __nv_bfloat16* __restrict__ C1) {
    extern __shared__ char sm[];
    const uint32_t base = smem_u32(sm);
    const int tid = threadIdx.x;
    const int bm = blockIdx.y * 128;
    const int bn = blockIdx.x * 128;
    const __nv_bfloat16* A = blockIdx.z ? A1 : A0;
    const __nv_bfloat16* B = blockIdx.z ? B1 : B0;
    __nv_bfloat16* Cb = blockIdx.z ? C1 : C0;
    const int warp = tid >> 5, lane = tid & 31;
    const int wm = warp & 3;
    const int wn = warp >> 2;

    float acc[2][8][4];
#pragma unroll
    for (int i = 0; i < 2; i++)
#pragma unroll
        for (int j = 0; j < 8; j++)
#pragma unroll
            for (int k = 0; k < 4; k++) acc[i][j][k] = 0.f;

    g1_load(base, A, B, bm, bn, 0, tid);
    CP_COMMIT();
    g1_load(base + S1B, A, B, bm, bn, 64, tid);
    CP_COMMIT();
    CP_WAIT(1);
    __syncthreads();

    const int a_row = (lane & 15);
    const int a_c16 = (lane >> 4) * 16;
    const int b_row = (lane & 7) + ((lane >> 4) << 3);
    const int b_c16 = ((lane >> 3) & 1) * 16;

    for (int c = 0; c < NCH1; c++) {
        if (c + 2 < NCH1) {
            g1_load(base + ((c + 2) % 3) * S1B, A, B, bm, bn, (c + 2) * 64, tid);
            CP_COMMIT();
        }

        const uint32_t tA = base + (c % 3) * S1B;
        const uint32_t tB = tA + T1B;

#pragma unroll
        for (int ks = 0; ks < 4; ks++) {
            uint32_t ah[2][4];
#pragma unroll
            for (int mf = 0; mf < 2; mf++)
                LDSM4(ah[mf][0], ah[mf][1], ah[mf][2], ah[mf][3],
                      tA + (wm * 32 + mf * 16 + a_row) * (T1ST * 2) + ks * 32 + a_c16);
#pragma unroll
            for (int nf4 = 0; nf4 < 4; nf4++) {
                uint32_t bh[4];
                LDSM4(bh[0], bh[1], bh[2], bh[3],
                      tB + (wn * 64 + nf4 * 16 + b_row) * (T1ST * 2) + ks * 32 + b_c16);
#pragma unroll
                for (int mf = 0; mf < 2; mf++) {
                    MMA_BF16(acc[mf][nf4 * 2],     ah[mf], bh[0], bh[1]);
                    MMA_BF16(acc[mf][nf4 * 2 + 1], ah[mf], bh[2], bh[3]);
                }
            }
        }

        if (c + 2 < NCH1)      { CP_WAIT(1); }
        else if (c + 1 < NCH1) { CP_WAIT(0); }
        __syncthreads();
    }

#pragma unroll
    for (int mf = 0; mf < 2; mf++) {
        int r0 = bm + wm * 32 + mf * 16 + (lane >> 2);
#pragma unroll
        for (int nf = 0; nf < 8; nf++) {
            int cc = bn + wn * 64 + nf * 8 + (lane & 3) * 2;
            *(uint32_t*)&Cb[(size_t)r0 * DIMC + cc] =
                packbf(acc[mf][nf][0], acc[mf][nf][1]);
            *(uint32_t*)&Cb[(size_t)(r0 + 8) * DIMC + cc] =
                packbf(acc[mf][nf][2], acc[mf][nf][3]);
        }
    }
}

// ---------------- tensor-core flash attention ----------------
#define FKST   144
#define FQTB   (128 * FKST)
#define FSTGB  (2 * FQTB + 512)
#define FSCL   0.03125f

__device__ __forceinline__ void flash_load_stage(
    uint32_t sb, const __nv_bfloat16* __restrict__ Kb,
    const __nv_bfloat16* __restrict__ Vb, const float* __restrict__ mKF,
    int bz, int h, int k0, int tid) {
#pragma unroll
    for (int i = 0; i < 4; i++) {
        int idx = tid + i * 256;
        int r = idx >> 3, cq = idx & 7;
        size_t go = ((size_t)(bz * SEQ + k0 + r)) * DIMC + h * DHD + cq * 8;
        uint32_t doff = (uint32_t)(r * FKST + cq * 16);
        CP_ASYNC16(sb + doff,        Kb + go);
        CP_ASYNC16(sb + FQTB + doff, Vb + go);
    }
    if (tid < 32)
        CP_ASYNC16(sb + 2 * FQTB + tid * 16, mKF + bz * SEQ + k0 + tid * 4);
}

__global__ __launch_bounds__(256) void flash_mma(
    const __nv_bfloat16* __restrict__ Qb, const __nv_bfloat16* __restrict__ Kb,
    const __nv_bfloat16* __restrict__ Vb, float* __restrict__ Out) {
    extern __shared__ char sm[];
    const uint32_t qbase = smem_u32(sm);
    const uint32_t sbase = qbase + FQTB;
    const float* mKF = g_maskKF;

    const int tid = threadIdx.x;
    const int bz = blockIdx.z, h = blockIdx.y;
    const int q0 = blockIdx.x * 128;
    const int lane = tid & 31, wq = tid >> 5;

#pragma unroll
    for (int i = 0; i < 4; i++) {
        int idx = tid + i * 256;
        int r = idx >> 3, cq = idx & 7;
        CP_ASYNC16(qbase + r * FKST + cq * 16,
                   Qb + ((size_t)(bz * SEQ + q0 + r)) * DIMC + h * DHD + cq * 8);
    }
    flash_load_stage(sbase, Kb, Vb, mKF, bz, h, 0, tid);
    CP_COMMIT();
    CP_WAIT(0);
    __syncthreads();

    const int a_row = (lane & 15);
    const int a_c16 = (lane >> 4) * 16;
    const int b_row = (lane & 7) + ((lane >> 4) << 3);
    const int b_c16 = ((lane >> 3) & 1) * 16;

    float m0 = -1e38f, m1 = -1e38f, l0 = 0.f, l1 = 0.f;
    float o[8][4];
#pragma unroll
    for (int i = 0; i < 8; i++)
#pragma unroll
        for (int j = 0; j < 4; j++) o[i][j] = 0.f;
    uint32_t qa[4][4];
#pragma unroll
    for (int ks = 0; ks < 4; ks++)
        LDSM4(qa[ks][0], qa[ks][1], qa[ks][2], qa[ks][3],
              qbase + (wq * 16 + a_row) * FKST + ks * 32 + a_c16);

    for (int c = 0; c < SEQ / 128; c++) {
        if (c + 1 < SEQ / 128) {
            flash_load_stage(sbase + ((c + 1) & 1) * FSTGB, Kb, Vb, mKF,
                             bz, h, (c + 1) * 128, tid);
            CP_COMMIT();
        }

        const uint32_t Kt = sbase + (c & 1) * FSTGB;
        const uint32_t Vt = Kt + FQTB;
        const uint32_t Mq = Kt + 2 * FQTB;

        float s[16][4];
#pragma unroll
        for (int i = 0; i < 16; i++)
#pragma unroll
            for (int j = 0; j < 4; j++) s[i][j] = 0.f;

#pragma unroll
        for (int kb = 0; kb < 8; kb++) {
#pragma unroll
            for (int ks = 0; ks < 4; ks++) {
                uint32_t b0, b1, b2, b3;
                LDSM4(b0, b1, b2, b3,
                      Kt + (kb * 16 + b_row) * FKST + ks * 32 + b_c16);
                MMA_BF16(s[2 * kb],     qa[ks], b0, b1);
                MMA_BF16(s[2 * kb + 1], qa[ks], b2, b3);
            }
        }

#pragma unroll
        for (int nf = 0; nf < 16; nf++) {
            float2 ma;
            asm volatile("ld.shared.v2.f32 {%0,%1}, [%2];"
                         : "=f"(ma.x), "=f"(ma.y)
                         : "r"(Mq + (uint32_t)(nf * 32 + (lane & 3) * 8)));
            s[nf][0] += ma.x; s[nf][1] += ma.y;
            s[nf][2] += ma.x; s[nf][3] += ma.y;
        }

        float mx0 = m0, mx1 = m1;
#pragma unroll
        for (int nf = 0; nf < 16; nf++) {
            mx0 = fmaxf(mx0, fmaxf(s[nf][0], s[nf][1]));
            mx1 = fmaxf(mx1, fmaxf(s[nf][2], s[nf][3]));
        }
#pragma unroll
        for (int off = 1; off <= 2; off <<= 1) {
            mx0 = fmaxf(mx0, __shfl_xor_sync(0xffffffffu, mx0, off));
            mx1 = fmaxf(mx1, __shfl_xor_sync(0xffffffffu, mx1, off));
        }
        const float c0 = __expf((m0 - mx0) * FSCL);
        const float c1 = __expf((m1 - mx1) * FSCL);
        m0 = mx0; m1 = mx1;
        l0 *= c0; l1 *= c1;
#pragma unroll
        for (int nf = 0; nf < 8; nf++) {
            o[nf][0] *= c0; o[nf][1] *= c0;
            o[nf][2] *= c1; o[nf][3] *= c1;
        }

        const float mk0 = mx0 * FSCL, mk1 = mx1 * FSCL;
        float ls0 = 0.f, ls1 = 0.f;
#pragma unroll
        for (int nf = 0; nf < 16; nf++) {
            s[nf][0] = __expf(fmaf(s[nf][0], FSCL, -mk0));
            s[nf][1] = __expf(fmaf(s[nf][1], FSCL, -mk0));
            s[nf][2] = __expf(fmaf(s[nf][2], FSCL, -mk1));
            s[nf][3] = __expf(fmaf(s[nf][3], FSCL, -mk1));
            ls0 += s[nf][0] + s[nf][1];
            ls1 += s[nf][2] + s[nf][3];
        }
#pragma unroll
        for (int off = 1; off <= 2; off <<= 1) {
            ls0 += __shfl_xor_sync(0xffffffffu, ls0, off);
            ls1 += __shfl_xor_sync(0xffffffffu, ls1, off);
        }
        l0 += ls0; l1 += ls1;

#pragma unroll
        for (int kv = 0; kv < 8; kv++) {
            uint32_t pa[4];
            pa[0] = packbf(s[2 * kv][0],     s[2 * kv][1]);
            pa[1] = packbf(s[2 * kv][2],     s[2 * kv][3]);
            pa[2] = packbf(s[2 * kv + 1][0], s[2 * kv + 1][1]);
            pa[3] = packbf(s[2 * kv + 1][2], s[2 * kv + 1][3]);
#pragma unroll
            for (int dp = 0; dp < 4; dp++) {
                uint32_t v0, v1, v2, v3;
                LDSM4T(v0, v1, v2, v3,
                       Vt + (kv * 16 + a_row) * FKST + dp * 32 + a_c16);
                MMA_BF16(o[2 * dp],     pa, v0, v1);
                MMA_BF16(o[2 * dp + 1], pa, v2, v3);
            }
        }

        if (c + 1 < SEQ / 128) CP_WAIT(0);
        __syncthreads();
    }

    const float inv0 = 1.f / l0, inv1 = 1.f / l1;
    const int row0 = bz * SEQ + q0 + wq * 16 + (lane >> 2);
#pragma unroll
    for (int nf = 0; nf < 8; nf++) {
        int cc = h * DHD + nf * 8 + (lane & 3) * 2;
        *(float2*)&Out[(size_t)row0 * DIMC + cc] =
            make_float2(o[nf][0] * inv0, o[nf][1] * inv0);
        *(float2*)&Out[(size_t)(row0 + 8) * DIMC + cc] =
            make_float2(o[nf][2] * inv1, o[nf][3] * inv1);
    }
}

// ---------------- layernorm helpers ----------------
__device__ __forceinline__ void block_reduce2(float& s, float& ss) {
    __shared__ float r1[8], r2[8];
#pragma unroll
    for (int o = 16; o > 0; o >>= 1) {
        s  += __shfl_xor_sync(0xffffffffu, s, o);
        ss += __shfl_xor_sync(0xffffffffu, ss, o);
    }
    int w = threadIdx.x >> 5;
    if ((threadIdx.x & 31) == 0) { r1[w] = s; r2[w] = ss; }
    __syncthreads();
    s = 0.f; ss = 0.f;
#pragma unroll
    for (int i = 0; i < 8; i++) { s += r1[i]; ss += r2[i]; }
}

__global__ __launch_bounds__(256) void ln1_kernel(const float* __restrict__ A,
                                                  const float* __restrict__ Bv,
                                                  const float* __restrict__ gm,
                                                  const float* __restrict__ be,
                                                  float* __restrict__ X,
                                                  __nv_bfloat16* __restrict__ Xh,
                                                  __nv_bfloat16* __restrict__ Xl) {
    const int row = blockIdx.x;
    float* xo = X + (size_t)row * DIMC;
    __nv_bfloat16* xh = Xh + (size_t)row * DIMC;
    __nv_bfloat16* xl = Xl + (size_t)row * DIMC;
    if (g_maskQ[row]) {
        for (int i = threadIdx.x; i < DIMC; i += 256) {
            xo[i] = 0.f;
            xh[i] = __float2bfloat16(0.f);
            xl[i] = __float2bfloat16(0.f);
        }
        return;
    }
    const float* a  = A + (size_t)row * DIMC;
    const float* bv = Bv + (size_t)row * DIMC;
    float vals[4];
    float s = 0.f, ss = 0.f;
#pragma unroll
    for (int t = 0; t < 4; t++) {
        int i = threadIdx.x + t * 256;
        float v = a[i] + bv[i];
        vals[t] = v; s += v; ss += v * v;
    }
    block_reduce2(s, ss);
    float mean = s * (1.f / DIMC);
    float var  = ss * (1.f / DIMC) - mean * mean;
    float rstd = rsqrtf(var + 1e-5f);
#pragma unroll
    for (int t = 0; t < 4; t++) {
        int i = threadIdx.x + t * 256;
        float v = (vals[t] - mean) * rstd * gm[i] + be[i];
        xo[i] = v;
        __nv_bfloat16 hh = __float2bfloat16(v);
        xh[i] = hh;
        xl[i] = __float2bfloat16(v - __bfloat162float(hh));
    }
}

__device__ __forceinline__ float gelu_exact(float x) {
    return 0.5f * x * (1.f + erff(x * 0.70710678118654752f));
}

__global__ __launch_bounds__(256) void final_kernel(const float* __restrict__ X,
                                                    const float* __restrict__ Hx,
                                                    const float* __restrict__ gm,
                                                    const float* __restrict__ be,
                                                    float* __restrict__ out) {
    const int row = blockIdx.x;
    float* o = out + (size_t)row * DIMC;
    if (g_maskQ[row]) {
        for (int i = threadIdx.x; i < DIMC; i += 256) o[i] = 0.f;
        return;
    }
    const float* x = X + (size_t)row * DIMC;
    const float* hv = Hx + (size_t)row * DIMC;
    float vals[4];
    float s = 0.f, ss = 0.f;
#pragma unroll
    for (int t = 0; t < 4; t++) {
        int i = threadIdx.x + t * 256;
        float v = x[i] + gelu_exact(hv[i]);
        vals[t] = v; s += v; ss += v * v;
    }
    block_reduce2(s, ss);
    float mean = s * (1.f / DIMC);
    float var  = ss * (1.f / DIMC) - mean * mean;
    float rstd = rsqrtf(var + 1e-5f);
#pragma unroll
    for (int t = 0; t < 4; t++) {
        int i = threadIdx.x + t * 256;
        o[i] = (vals[t] - mean) * rstd * gm[i] + be[i];
    }
}

// ---------------- launch ----------------
extern "C" void kernel_launch(void* const* d_in, const int* in_sizes, int n_in,
                              void* d_out, int out_size) {
    const float* Q    = (const float*)d_in[0];
    const float* K    = (const float*)d_in[1];
    const float* V    = (const float*)d_in[2];
    const float* Wq   = (const float*)d_in[3];
    const float* Wk   = (const float*)d_in[4];
    const float* Wv   = (const float*)d_in[5];
    const float* Wo   = (const float*)d_in[6];
    const float* ln1g = (const float*)d_in[7];
    const float* ln1b = (const float*)d_in[8];
    const float* ln2g = (const float*)d_in[9];
    const float* ln2b = (const float*)d_in[10];
    const void*  mq   = d_in[11];
    const void*  mk   = d_in[12];
    float* out = (float*)d_out;

    void *pQp, *pAt, *pX, *pH, *pAh, *pAl, *pIh, *pIh2, *pWh, *pWl, *pQb, *pKb, *pVb;
    cudaGetSymbolAddress(&pQp, g_Qp);
    cudaGetSymbolAddress(&pAt, g_attn);
    cudaGetSymbolAddress(&pX,  g_X);
    cudaGetSymbolAddress(&pH,  g_Hb);
    cudaGetSymbolAddress(&pAh, g_Ah);
    cudaGetSymbolAddress(&pAl, g_Al);
    cudaGetSymbolAddress(&pIh, g_Ih);
    cudaGetSymbolAddress(&pIh2, g_Ih2);
    cudaGetSymbolAddress(&pWh, g_Wh);
    cudaGetSymbolAddress(&pWl, g_Wl);
    cudaGetSymbolAddress(&pQb, g_Qb);
    cudaGetSymbolAddress(&pKb, g_Kb);
    cudaGetSymbolAddress(&pVb, g_Vb);
    __nv_bfloat16* Ahp = (__nv_bfloat16*)pAh;
    __nv_bfloat16* Alp = (__nv_bfloat16*)pAl;
    __nv_bfloat16* Ihp = (__nv_bfloat16*)pIh;
    __nv_bfloat16* Ih2p = (__nv_bfloat16*)pIh2;
    __nv_bfloat16* Whp = (__nv_bfloat16*)pWh;
    __nv_bfloat16* Wlp = (__nv_bfloat16*)pWl;
    const int WSZ = DIMC * DIMC;
    const int WN4 = WSZ / 4;          // 262144
    const int AN4 = ROWS * DIMC / 4;  // 1048576

    prep_mask_kernel<<<1, 256>>>(mq, mk);

    // weights: Wq, Wo hi+lo; Wk, Wv hi only (one batched launch)
    {
        ConvJobs4 jw;
        jw.j[0] = {Wq, Whp + 0 * (size_t)WSZ, Wlp + 0 * (size_t)WSZ, WN4};
        jw.j[1] = {Wk, Whp + 1 * (size_t)WSZ, (__nv_bfloat16*)nullptr, WN4};
        jw.j[2] = {Wv, Whp + 2 * (size_t)WSZ, (__nv_bfloat16*)nullptr, WN4};
        jw.j[3] = {Wo, Whp + 3 * (size_t)WSZ, Wlp + 3 * (size_t)WSZ, WN4};
        conv_batch<<<dim3(WN4 / 256, 1, 4), 256>>>(jw);
    }
    // inputs: Q hi+lo; K, V hi only (one batched launch)
    {
        ConvJobs4 ji;
        ji.j[0] = {Q, Ahp, Alp, AN4};
        ji.j[1] = {K, Ihp, (__nv_bfloat16*)nullptr, AN4};
        ji.j[2] = {V, Ih2p, (__nv_bfloat16*)nullptr, AN4};
        ji.j[3] = {Q, Ahp, (__nv_bfloat16*)nullptr, 0};   // inert
        conv_batch<<<dim3(AN4 / 256, 1, 3), 256>>>(ji);
    }

    const size_t g3smem = 3 * BUFB;   // 122880
    cudaFuncSetAttribute(gemm_mma3, cudaFuncAttributeMaxDynamicSharedMemorySize,
                         (int)g3smem);
    const size_t g1smem = 3 * S1B;    // 110592
    cudaFuncSetAttribute(gemm_mma1, cudaFuncAttributeMaxDynamicSharedMemorySize,
                         (int)g1smem);
    dim3 gg(DIMC / 128, ROWS / 128);  // (8, 32)

    // Q projection: full 3-pass (fp32 Qp feeds residual) + bf16 Qb for flash
    gemm_mma3<<<gg, 256, g3smem>>>(Ahp, Alp, Whp + 0 * (size_t)WSZ,
                                   Wlp + 0 * (size_t)WSZ, (float*)pQp,
                                   (__nv_bfloat16*)pQb);
    // K and V projections: 1-pass bf16 (outputs only ever consumed as bf16)
    gemm_mma1<<<dim3(8, 32, 2), 256, g1smem>>>(
        Ihp,  Whp + 1 * (size_t)WSZ, (__nv_bfloat16*)pKb,
        Ih2p, Whp + 2 * (size_t)WSZ, (__nv_bfloat16*)pVb);

    const size_t fsmem = FQTB + 2 * FSTGB;  // 93184
    cudaFuncSetAttribute(flash_mma, cudaFuncAttributeMaxDynamicSharedMemorySize,
                         (int)fsmem);
    flash_mma<<<dim3(SEQ / 128, NH, BB), 256, fsmem>>>(
        (const __nv_bfloat16*)pQb, (const __nv_bfloat16*)pKb,
        (const __nv_bfloat16*)pVb, (float*)pAt);

    ln1_kernel<<<ROWS, 256>>>((const float*)pQp, (const float*)pAt, ln1g, ln1b,
                              (float*)pX, Ahp, Alp);

    gemm_mma3<<<gg, 256, g3smem>>>(Ahp, Alp, Whp + 3 * (size_t)WSZ,
                                   Wlp + 3 * (size_t)WSZ, (float*)pH,
                                   (__nv_bfloat16*)nullptr);

    final_kernel<<<ROWS, 256>>>((const float*)pX, (const float*)pH, ln2g, ln2b, out);
}

// round 9
// speedup vs baseline: 4.7041x; 1.0849x over previous
#include <cuda_runtime.h>
#include <cuda_bf16.h>
#include <math.h>
#include <stdint.h>

#define BB   4
#define SEQ  1024
#define DIMC 1024
#define NH   16
#define DHD  64
#define ROWS (BB * SEQ)      // 4096

// ---------------- scratch (device globals: allocation-guard safe) ----------------
__device__ float g_Qp[ROWS * DIMC];
__device__ float g_attn[ROWS * DIMC];
__device__ float g_X[ROWS * DIMC];
__device__ float g_Hb[ROWS * DIMC];
__device__ int   g_maskQ[ROWS];
__device__ float g_maskKF[ROWS];    // 0 or -1e38 addend
// split-bf16 GEMM operands
__device__ __nv_bfloat16 g_Ah[ROWS * DIMC];
__device__ __nv_bfloat16 g_Al[ROWS * DIMC];
__device__ __nv_bfloat16 g_Ih[ROWS * DIMC];    // K input hi
__device__ __nv_bfloat16 g_Ih2[ROWS * DIMC];   // V input hi
__device__ __nv_bfloat16 g_Wh[4][DIMC * DIMC];
__device__ __nv_bfloat16 g_Wl[4][DIMC * DIMC];
// bf16 projected tensors for flash
__device__ __nv_bfloat16 g_Qb[ROWS * DIMC];
__device__ __nv_bfloat16 g_Kb[ROWS * DIMC];
__device__ __nv_bfloat16 g_Vb[ROWS * DIMC];

// ---------------- PTX helpers (base compute_103-safe only) ----------------
__device__ __forceinline__ uint32_t smem_u32(const void* p) {
    uint32_t a;
    asm("{ .reg .u64 t; cvta.to.shared.u64 t, %1; cvt.u32.u64 %0, t; }"
        : "=r"(a) : "l"(p));
    return a;
}

#define CP_ASYNC16(dst, src) \
    asm volatile("cp.async.cg.shared.global [%0], [%1], 16;" \
                 :: "r"(dst), "l"(src) : "memory")
#define CP_COMMIT()  asm volatile("cp.async.commit_group;" ::: "memory")
#define CP_WAIT(n)   asm volatile("cp.async.wait_group %0;" :: "n"(n) : "memory")

#define LDSM4(r0, r1, r2, r3, addr) \
    asm volatile("ldmatrix.sync.aligned.m8n8.x4.shared.b16 {%0,%1,%2,%3}, [%4];" \
                 : "=r"(r0), "=r"(r1), "=r"(r2), "=r"(r3) : "r"(addr))

#define LDSM4T(r0, r1, r2, r3, addr) \
    asm volatile("ldmatrix.sync.aligned.m8n8.x4.trans.shared.b16 {%0,%1,%2,%3}, [%4];" \
                 : "=r"(r0), "=r"(r1), "=r"(r2), "=r"(r3) : "r"(addr))

#define MMA_BF16(d, a, b0, b1) \
    asm volatile("mma.sync.aligned.m16n8k16.row.col.f32.bf16.bf16.f32 " \
                 "{%0,%1,%2,%3}, {%4,%5,%6,%7}, {%8,%9}, {%0,%1,%2,%3};" \
                 : "+f"((d)[0]), "+f"((d)[1]), "+f"((d)[2]), "+f"((d)[3]) \
                 : "r"((a)[0]), "r"((a)[1]), "r"((a)[2]), "r"((a)[3]), \
                   "r"(b0), "r"(b1))

__device__ __forceinline__ uint32_t packbf(float lo, float hi) {
    __nv_bfloat162 v = __floats2bfloat162_rn(lo, hi);
    return *(uint32_t*)&v;
}

// ---------------- mask canonicalization ----------------
__device__ __forceinline__ int mask_is_bytes(const unsigned int* w) {
    bool wordlike = true;
#pragma unroll
    for (int i = 0; i < 32; i++) {
        unsigned int v = w[i];
        if (v != 0u && v != 1u && v != 0x3F800000u) wordlike = false;
    }
    return wordlike ? 0 : 1;
}

__global__ void prep_mask_kernel(const void* mq, const void* mk) {
    int bq = mask_is_bytes((const unsigned int*)mq);
    int bk = mask_is_bytes((const unsigned int*)mk);
    for (int i = threadIdx.x; i < ROWS; i += blockDim.x) {
        int vq = bq ? (((const unsigned char*)mq)[i] != 0)
                    : (((const unsigned int*)mq)[i] != 0u);
        int vk = bk ? (((const unsigned char*)mk)[i] != 0)
                    : (((const unsigned int*)mk)[i] != 0u);
        g_maskQ[i]  = vq;
        g_maskKF[i] = vk ? -1e38f : 0.f;
    }
}

// ---------------- batched fp32 -> bf16 (hi [, lo]) conversion ----------------
struct ConvJob { const float* src; __nv_bfloat16* hi; __nv_bfloat16* lo; int n4; };
struct ConvJobs4 { ConvJob j[4]; };

__global__ __launch_bounds__(256) void conv_batch(ConvJobs4 jobs) {
    const ConvJob jb = jobs.j[blockIdx.z];
    int i = blockIdx.x * 256 + threadIdx.x;
    if (i >= jb.n4) return;
    float4 v = ((const float4*)jb.src)[i];
    __nv_bfloat16 h0 = __float2bfloat16(v.x);
    __nv_bfloat16 h1 = __float2bfloat16(v.y);
    __nv_bfloat16 h2 = __float2bfloat16(v.z);
    __nv_bfloat16 h3 = __float2bfloat16(v.w);
    ((__nv_bfloat162*)jb.hi)[2 * i]     = __nv_bfloat162(h0, h1);
    ((__nv_bfloat162*)jb.hi)[2 * i + 1] = __nv_bfloat162(h2, h3);
    if (jb.lo) {
        __nv_bfloat16 l0 = __float2bfloat16(v.x - __bfloat162float(h0));
        __nv_bfloat16 l1 = __float2bfloat16(v.y - __bfloat162float(h1));
        __nv_bfloat16 l2 = __float2bfloat16(v.z - __bfloat162float(h2));
        __nv_bfloat16 l3 = __float2bfloat16(v.w - __bfloat162float(h3));
        ((__nv_bfloat162*)jb.lo)[2 * i]     = __nv_bfloat162(l0, l1);
        ((__nv_bfloat162*)jb.lo)[2 * i + 1] = __nv_bfloat162(l2, l3);
    }
}

// ---------------- 3-pass split-bf16 GEMM (Q and Wo projections) ----------------
// C = A * B^T: Ahi*Bhi + Ahi*Blo + Alo*Bhi. CTA 128x128, warp 32x64.
// K-chunk 32, 2-stage cp.async (2 CTAs/SM for cross-CTA latency hiding).
#define MST   40
#define TILEB (128 * MST * 2)        // 10240
#define BUFB  (4 * TILEB)            // 40960 per stage
#define NCH   (DIMC / 32)            // 32

__device__ __forceinline__ void g3_load(
    uint32_t sbase, const __nv_bfloat16* __restrict__ Ah,
    const __nv_bfloat16* __restrict__ Al, const __nv_bfloat16* __restrict__ Bh,
    const __nv_bfloat16* __restrict__ Bl, int bm, int bn, int k0, int tid) {
#pragma unroll
    for (int h = 0; h < 2; h++) {
        int idx = tid + h * 256;
        int r = idx >> 2, q = idx & 3;
        uint32_t doff = (uint32_t)(r * (MST * 2) + q * 16);
        size_t ga = ((size_t)(bm + r) << 10) + k0 + (q << 3);
        size_t gb = ((size_t)(bn + r) << 10) + k0 + (q << 3);
        CP_ASYNC16(sbase + doff,             Ah + ga);
        CP_ASYNC16(sbase + TILEB + doff,     Al + ga);
        CP_ASYNC16(sbase + 2 * TILEB + doff, Bh + gb);
        CP_ASYNC16(sbase + 3 * TILEB + doff, Bl + gb);
    }
}

__global__ __launch_bounds__(256, 2) void gemm_mma3(
    const __nv_bfloat16* __restrict__ Ah, const __nv_bfloat16* __restrict__ Al,
    const __nv_bfloat16* __restrict__ Bh, const __nv_bfloat16* __restrict__ Bl,
    float* __restrict__ Cf, __nv_bfloat16* __restrict__ Cb) {
    extern __shared__ char sm[];
    const uint32_t base = smem_u32(sm);
    const int tid = threadIdx.x;
    const int bm = blockIdx.y * 128;
    const int bn = blockIdx.x * 128;
    const int warp = tid >> 5, lane = tid & 31;
    const int wm = warp & 3;
    const int wn = warp >> 2;

    float acc[2][8][4];
#pragma unroll
    for (int i = 0; i < 2; i++)
#pragma unroll
        for (int j = 0; j < 8; j++)
#pragma unroll
            for (int k = 0; k < 4; k++) acc[i][j][k] = 0.f;

    g3_load(base, Ah, Al, Bh, Bl, bm, bn, 0, tid);
    CP_COMMIT();

    const int a_row = (lane & 15);
    const int a_k   = (lane >> 4) * 8;
    const int b_row = (lane & 7) + ((lane >> 4) << 3);
    const int b_k   = ((lane >> 3) & 1) * 8;

    for (int c = 0; c < NCH; c++) {
        if (c + 1 < NCH) {
            g3_load(base + ((c + 1) & 1) * BUFB, Ah, Al, Bh, Bl,
                    bm, bn, (c + 1) * 32, tid);
            CP_COMMIT();
            CP_WAIT(1);
        } else {
            CP_WAIT(0);
        }
        __syncthreads();

        const uint32_t bu = base + (c & 1) * BUFB;
        const uint32_t tAh = bu;
        const uint32_t tAl = bu + TILEB;
        const uint32_t tBh = bu + 2 * TILEB;
        const uint32_t tBl = bu + 3 * TILEB;

#pragma unroll
        for (int ks = 0; ks < 2; ks++) {
            uint32_t ah[2][4], al[2][4];
            const int kk = ks * 16 + a_k;
#pragma unroll
            for (int mf = 0; mf < 2; mf++) {
                uint32_t ra = (uint32_t)((wm * 32 + mf * 16 + a_row) * (MST * 2) + kk * 2);
                LDSM4(ah[mf][0], ah[mf][1], ah[mf][2], ah[mf][3], tAh + ra);
                LDSM4(al[mf][0], al[mf][1], al[mf][2], al[mf][3], tAl + ra);
            }
#pragma unroll
            for (int nf4 = 0; nf4 < 4; nf4++) {
                uint32_t bh[4], bl[4];
                uint32_t rb = (uint32_t)((wn * 64 + nf4 * 16 + b_row) * (MST * 2) +
                                         (ks * 16 + b_k) * 2);
                LDSM4(bh[0], bh[1], bh[2], bh[3], tBh + rb);
                LDSM4(bl[0], bl[1], bl[2], bl[3], tBl + rb);
#pragma unroll
                for (int mf = 0; mf < 2; mf++) {
                    MMA_BF16(acc[mf][nf4 * 2],     ah[mf], bh[0], bh[1]);
                    MMA_BF16(acc[mf][nf4 * 2],     ah[mf], bl[0], bl[1]);
                    MMA_BF16(acc[mf][nf4 * 2],     al[mf], bh[0], bh[1]);
                    MMA_BF16(acc[mf][nf4 * 2 + 1], ah[mf], bh[2], bh[3]);
                    MMA_BF16(acc[mf][nf4 * 2 + 1], ah[mf], bl[2], bl[3]);
                    MMA_BF16(acc[mf][nf4 * 2 + 1], al[mf], bh[2], bh[3]);
                }
            }
        }
        __syncthreads();
    }

#pragma unroll
    for (int mf = 0; mf < 2; mf++) {
        int r0 = bm + wm * 32 + mf * 16 + (lane >> 2);
#pragma unroll
        for (int nf = 0; nf < 8; nf++) {
            int cc = bn + wn * 64 + nf * 8 + (lane & 3) * 2;
            if (Cf) {
                *(float2*)&Cf[(size_t)r0 * DIMC + cc] =
                    make_float2(acc[mf][nf][0], acc[mf][nf][1]);
                *(float2*)&Cf[(size_t)(r0 + 8) * DIMC + cc] =
                    make_float2(acc[mf][nf][2], acc[mf][nf][3]);
            }
            if (Cb) {
                *(uint32_t*)&Cb[(size_t)r0 * DIMC + cc] =
                    packbf(acc[mf][nf][0], acc[mf][nf][1]);
                *(uint32_t*)&Cb[(size_t)(r0 + 8) * DIMC + cc] =
                    packbf(acc[mf][nf][2], acc[mf][nf][3]);
            }
        }
    }
}

// ---------------- 1-pass bf16 GEMM (K and V projections, batched) ----------------
// Cb = bf16(Ah * Bh^T). K-chunk 64, 2-stage (2 CTAs/SM). z selects job.
#define T1ST  72                      // halves per row (144 B)
#define T1B   (128 * T1ST * 2)        // 18432
#define S1B   (2 * T1B)               // 36864 per stage
#define NCH1  (DIMC / 64)             // 16

__device__ __forceinline__ void g1_load(
    uint32_t sbase, const __nv_bfloat16* __restrict__ A,
    const __nv_bfloat16* __restrict__ B, int bm, int bn, int k0, int tid) {
#pragma unroll
    for (int i = 0; i < 4; i++) {
        int idx = tid + i * 256;
        int r = idx >> 3, q = idx & 7;
        uint32_t doff = (uint32_t)(r * (T1ST * 2) + q * 16);
        CP_ASYNC16(sbase + doff,       A + (((size_t)(bm + r)) << 10) + k0 + (q << 3));
        CP_ASYNC16(sbase + T1B + doff, B + (((size_t)(bn + r)) << 10) + k0 + (q << 3));
    }
}

__global__ __launch_bounds__(256, 2) void gemm_mma1(
    const __nv_bfloat16* __restrict__ A0, const __nv_bfloat16* __restrict__ B0,
    __nv_bfloat16* __restrict__ C0,
    const __nv_bfloat16* __restrict__ A1, const __nv_bfloat16* __restrict__ B1,
    __nv_bfloat16* __restrict__ C1) {
    extern __shared__ char sm[];
    const uint32_t base = smem_u32(sm);
    const int tid = threadIdx.x;
    const int bm = blockIdx.y * 128;
    const int bn = blockIdx.x * 128;
    const __nv_bfloat16* A = blockIdx.z ? A1 : A0;
    const __nv_bfloat16* B = blockIdx.z ? B1 : B0;
    __nv_bfloat16* Cb = blockIdx.z ? C1 : C0;
    const int warp = tid >> 5, lane = tid & 31;
    const int wm = warp & 3;
    const int wn = warp >> 2;

    float acc[2][8][4];
#pragma unroll
    for (int i = 0; i < 2; i++)
#pragma unroll
        for (int j = 0; j < 8; j++)
#pragma unroll
            for (int k = 0; k < 4; k++) acc[i][j][k] = 0.f;

    g1_load(base, A, B, bm, bn, 0, tid);
    CP_COMMIT();

    const int a_row = (lane & 15);
    const int a_c16 = (lane >> 4) * 16;
    const int b_row = (lane & 7) + ((lane >> 4) << 3);
    const int b_c16 = ((lane >> 3) & 1) * 16;

    for (int c = 0; c < NCH1; c++) {
        if (c + 1 < NCH1) {
            g1_load(base + ((c + 1) & 1) * S1B, A, B, bm, bn, (c + 1) * 64, tid);
            CP_COMMIT();
            CP_WAIT(1);
        } else {
            CP_WAIT(0);
        }
        __syncthreads();

        const uint32_t tA = base + (c & 1) * S1B;
        const uint32_t tB = tA + T1B;

#pragma unroll
        for (int ks = 0; ks < 4; ks++) {
            uint32_t ah[2][4];
#pragma unroll
            for (int mf = 0; mf < 2; mf++)
                LDSM4(ah[mf][0], ah[mf][1], ah[mf][2], ah[mf][3],
                      tA + (wm * 32 + mf * 16 + a_row) * (T1ST * 2) + ks * 32 + a_c16);
#pragma unroll
            for (int nf4 = 0; nf4 < 4; nf4++) {
                uint32_t bh[4];
                LDSM4(bh[0], bh[1], bh[2], bh[3],
                      tB + (wn * 64 + nf4 * 16 + b_row) * (T1ST * 2) + ks * 32 + b_c16);
#pragma unroll
                for (int mf = 0; mf < 2; mf++) {
                    MMA_BF16(acc[mf][nf4 * 2],     ah[mf], bh[0], bh[1]);
                    MMA_BF16(acc[mf][nf4 * 2 + 1], ah[mf], bh[2], bh[3]);
                }
            }
        }
        __syncthreads();
    }

#pragma unroll
    for (int mf = 0; mf < 2; mf++) {
        int r0 = bm + wm * 32 + mf * 16 + (lane >> 2);
#pragma unroll
        for (int nf = 0; nf < 8; nf++) {
            int cc = bn + wn * 64 + nf * 8 + (lane & 3) * 2;
            *(uint32_t*)&Cb[(size_t)r0 * DIMC + cc] =
                packbf(acc[mf][nf][0], acc[mf][nf][1]);
            *(uint32_t*)&Cb[(size_t)(r0 + 8) * DIMC + cc] =
                packbf(acc[mf][nf][2], acc[mf][nf][3]);
        }
    }
}

// ---------------- tensor-core flash attention ----------------
#define FKST   144
#define FQTB   (128 * FKST)
#define FSTGB  (2 * FQTB + 512)
#define FSCL   0.03125f

__device__ __forceinline__ void flash_load_stage(
    uint32_t sb, const __nv_bfloat16* __restrict__ Kb,
    const __nv_bfloat16* __restrict__ Vb, const float* __restrict__ mKF,
    int bz, int h, int k0, int tid) {
#pragma unroll
    for (int i = 0; i < 4; i++) {
        int idx = tid + i * 256;
        int r = idx >> 3, cq = idx & 7;
        size_t go = ((size_t)(bz * SEQ + k0 + r)) * DIMC + h * DHD + cq * 8;
        uint32_t doff = (uint32_t)(r * FKST + cq * 16);
        CP_ASYNC16(sb + doff,        Kb + go);
        CP_ASYNC16(sb + FQTB + doff, Vb + go);
    }
    if (tid < 32)
        CP_ASYNC16(sb + 2 * FQTB + tid * 16, mKF + bz * SEQ + k0 + tid * 4);
}

__global__ __launch_bounds__(256) void flash_mma(
    const __nv_bfloat16* __restrict__ Qb, const __nv_bfloat16* __restrict__ Kb,
    const __nv_bfloat16* __restrict__ Vb, float* __restrict__ Out) {
    extern __shared__ char sm[];
    const uint32_t qbase = smem_u32(sm);
    const uint32_t sbase = qbase + FQTB;
    const float* mKF = g_maskKF;

    const int tid = threadIdx.x;
    const int bz = blockIdx.z, h = blockIdx.y;
    const int q0 = blockIdx.x * 128;
    const int lane = tid & 31, wq = tid >> 5;

#pragma unroll
    for (int i = 0; i < 4; i++) {
        int idx = tid + i * 256;
        int r = idx >> 3, cq = idx & 7;
        CP_ASYNC16(qbase + r * FKST + cq * 16,
                   Qb + ((size_t)(bz * SEQ + q0 + r)) * DIMC + h * DHD + cq * 8);
    }
    flash_load_stage(sbase, Kb, Vb, mKF, bz, h, 0, tid);
    CP_COMMIT();
    CP_WAIT(0);
    __syncthreads();

    const int a_row = (lane & 15);
    const int a_c16 = (lane >> 4) * 16;
    const int b_row = (lane & 7) + ((lane >> 4) << 3);
    const int b_c16 = ((lane >> 3) & 1) * 16;

    float m0 = -1e38f, m1 = -1e38f, l0 = 0.f, l1 = 0.f;
    float o[8][4];
#pragma unroll
    for (int i = 0; i < 8; i++)
#pragma unroll
        for (int j = 0; j < 4; j++) o[i][j] = 0.f;
    uint32_t qa[4][4];
#pragma unroll
    for (int ks = 0; ks < 4; ks++)
        LDSM4(qa[ks][0], qa[ks][1], qa[ks][2], qa[ks][3],
              qbase + (wq * 16 + a_row) * FKST + ks * 32 + a_c16);

    for (int c = 0; c < SEQ / 128; c++) {
        if (c + 1 < SEQ / 128) {
            flash_load_stage(sbase + ((c + 1) & 1) * FSTGB, Kb, Vb, mKF,
                             bz, h, (c + 1) * 128, tid);
            CP_COMMIT();
        }

        const uint32_t Kt = sbase + (c & 1) * FSTGB;
        const uint32_t Vt = Kt + FQTB;
        const uint32_t Mq = Kt + 2 * FQTB;

        float s[16][4];
#pragma unroll
        for (int i = 0; i < 16; i++)
#pragma unroll
            for (int j = 0; j < 4; j++) s[i][j] = 0.f;

#pragma unroll
        for (int kb = 0; kb < 8; kb++) {
#pragma unroll
            for (int ks = 0; ks < 4; ks++) {
                uint32_t b0, b1, b2, b3;
                LDSM4(b0, b1, b2, b3,
                      Kt + (kb * 16 + b_row) * FKST + ks * 32 + b_c16);
                MMA_BF16(s[2 * kb],     qa[ks], b0, b1);
                MMA_BF16(s[2 * kb + 1], qa[ks], b2, b3);
            }
        }

#pragma unroll
        for (int nf = 0; nf < 16; nf++) {
            float2 ma;
            asm volatile("ld.shared.v2.f32 {%0,%1}, [%2];"
                         : "=f"(ma.x), "=f"(ma.y)
                         : "r"(Mq + (uint32_t)(nf * 32 + (lane & 3) * 8)));
            s[nf][0] += ma.x; s[nf][1] += ma.y;
            s[nf][2] += ma.x; s[nf][3] += ma.y;
        }

        float mx0 = m0, mx1 = m1;
#pragma unroll
        for (int nf = 0; nf < 16; nf++) {
            mx0 = fmaxf(mx0, fmaxf(s[nf][0], s[nf][1]));
            mx1 = fmaxf(mx1, fmaxf(s[nf][2], s[nf][3]));
        }
#pragma unroll
        for (int off = 1; off <= 2; off <<= 1) {
            mx0 = fmaxf(mx0, __shfl_xor_sync(0xffffffffu, mx0, off));
            mx1 = fmaxf(mx1, __shfl_xor_sync(0xffffffffu, mx1, off));
        }
        const float c0 = __expf((m0 - mx0) * FSCL);
        const float c1 = __expf((m1 - mx1) * FSCL);
        m0 = mx0; m1 = mx1;
        l0 *= c0; l1 *= c1;
#pragma unroll
        for (int nf = 0; nf < 8; nf++) {
            o[nf][0] *= c0; o[nf][1] *= c0;
            o[nf][2] *= c1; o[nf][3] *= c1;
        }

        const float mk0 = mx0 * FSCL, mk1 = mx1 * FSCL;
        float ls0 = 0.f, ls1 = 0.f;
#pragma unroll
        for (int nf = 0; nf < 16; nf++) {
            s[nf][0] = __expf(fmaf(s[nf][0], FSCL, -mk0));
            s[nf][1] = __expf(fmaf(s[nf][1], FSCL, -mk0));
            s[nf][2] = __expf(fmaf(s[nf][2], FSCL, -mk1));
            s[nf][3] = __expf(fmaf(s[nf][3], FSCL, -mk1));
            ls0 += s[nf][0] + s[nf][1];
            ls1 += s[nf][2] + s[nf][3];
        }
#pragma unroll
        for (int off = 1; off <= 2; off <<= 1) {
            ls0 += __shfl_xor_sync(0xffffffffu, ls0, off);
            ls1 += __shfl_xor_sync(0xffffffffu, ls1, off);
        }
        l0 += ls0; l1 += ls1;

#pragma unroll
        for (int kv = 0; kv < 8; kv++) {
            uint32_t pa[4];
            pa[0] = packbf(s[2 * kv][0],     s[2 * kv][1]);
            pa[1] = packbf(s[2 * kv][2],     s[2 * kv][3]);
            pa[2] = packbf(s[2 * kv + 1][0], s[2 * kv + 1][1]);
            pa[3] = packbf(s[2 * kv + 1][2], s[2 * kv + 1][3]);
#pragma unroll
            for (int dp = 0; dp < 4; dp++) {
                uint32_t v0, v1, v2, v3;
                LDSM4T(v0, v1, v2, v3,
                       Vt + (kv * 16 + a_row) * FKST + dp * 32 + a_c16);
                MMA_BF16(o[2 * dp],     pa, v0, v1);
                MMA_BF16(o[2 * dp + 1], pa, v2, v3);
            }
        }

        if (c + 1 < SEQ / 128) CP_WAIT(0);
        __syncthreads();
    }

    const float inv0 = 1.f / l0, inv1 = 1.f / l1;
    const int row0 = bz * SEQ + q0 + wq * 16 + (lane >> 2);
#pragma unroll
    for (int nf = 0; nf < 8; nf++) {
        int cc = h * DHD + nf * 8 + (lane & 3) * 2;
        *(float2*)&Out[(size_t)row0 * DIMC + cc] =
            make_float2(o[nf][0] * inv0, o[nf][1] * inv0);
        *(float2*)&Out[(size_t)(row0 + 8) * DIMC + cc] =
            make_float2(o[nf][2] * inv1, o[nf][3] * inv1);
    }
}

// ---------------- layernorm helpers ----------------
__device__ __forceinline__ void block_reduce2(float& s, float& ss) {
    __shared__ float r1[8], r2[8];
#pragma unroll
    for (int o = 16; o > 0; o >>= 1) {
        s  += __shfl_xor_sync(0xffffffffu, s, o);
        ss += __shfl_xor_sync(0xffffffffu, ss, o);
    }
    int w = threadIdx.x >> 5;
    if ((threadIdx.x & 31) == 0) { r1[w] = s; r2[w] = ss; }
    __syncthreads();
    s = 0.f; ss = 0.f;
#pragma unroll
    for (int i = 0; i < 8; i++) { s += r1[i]; ss += r2[i]; }
}

__global__ __launch_bounds__(256) void ln1_kernel(const float* __restrict__ A,
                                                  const float* __restrict__ Bv,
                                                  const float* __restrict__ gm,
                                                  const float* __restrict__ be,
                                                  float* __restrict__ X,
                                                  __nv_bfloat16* __restrict__ Xh,
                                                  __nv_bfloat16* __restrict__ Xl) {
    const int row = blockIdx.x;
    float* xo = X + (size_t)row * DIMC;
    __nv_bfloat16* xh = Xh + (size_t)row * DIMC;
    __nv_bfloat16* xl = Xl + (size_t)row * DIMC;
    if (g_maskQ[row]) {
        for (int i = threadIdx.x; i < DIMC; i += 256) {
            xo[i] = 0.f;
            xh[i] = __float2bfloat16(0.f);
            xl[i] = __float2bfloat16(0.f);
        }
        return;
    }
    const float* a  = A + (size_t)row * DIMC;
    const float* bv = Bv + (size_t)row * DIMC;
    float vals[4];
    float s = 0.f, ss = 0.f;
#pragma unroll
    for (int t = 0; t < 4; t++) {
        int i = threadIdx.x + t * 256;
        float v = a[i] + bv[i];
        vals[t] = v; s += v; ss += v * v;
    }
    block_reduce2(s, ss);
    float mean = s * (1.f / DIMC);
    float var  = ss * (1.f / DIMC) - mean * mean;
    float rstd = rsqrtf(var + 1e-5f);
#pragma unroll
    for (int t = 0; t < 4; t++) {
        int i = threadIdx.x + t * 256;
        float v = (vals[t] - mean) * rstd * gm[i] + be[i];
        xo[i] = v;
        __nv_bfloat16 hh = __float2bfloat16(v);
        xh[i] = hh;
        xl[i] = __float2bfloat16(v - __bfloat162float(hh));
    }
}

__device__ __forceinline__ float gelu_exact(float x) {
    return 0.5f * x * (1.f + erff(x * 0.70710678118654752f));
}

__global__ __launch_bounds__(256) void final_kernel(const float* __restrict__ X,
                                                    const float* __restrict__ Hx,
                                                    const float* __restrict__ gm,
                                                    const float* __restrict__ be,
                                                    float* __restrict__ out) {
    const int row = blockIdx.x;
    float* o = out + (size_t)row * DIMC;
    if (g_maskQ[row]) {
        for (int i = threadIdx.x; i < DIMC; i += 256) o[i] = 0.f;
        return;
    }
    const float* x = X + (size_t)row * DIMC;
    const float* hv = Hx + (size_t)row * DIMC;
    float vals[4];
    float s = 0.f, ss = 0.f;
#pragma unroll
    for (int t = 0; t < 4; t++) {
        int i = threadIdx.x + t * 256;
        float v = x[i] + gelu_exact(hv[i]);
        vals[t] = v; s += v; ss += v * v;
    }
    block_reduce2(s, ss);
    float mean = s * (1.f / DIMC);
    float var  = ss * (1.f / DIMC) - mean * mean;
    float rstd = rsqrtf(var + 1e-5f);
#pragma unroll
    for (int t = 0; t < 4; t++) {
        int i = threadIdx.x + t * 256;
        o[i] = (vals[t] - mean) * rstd * gm[i] + be[i];
    }
}

// ---------------- launch ----------------
extern "C" void kernel_launch(void* const* d_in, const int* in_sizes, int n_in,
                              void* d_out, int out_size) {
    const float* Q    = (const float*)d_in[0];
    const float* K    = (const float*)d_in[1];
    const float* V    = (const float*)d_in[2];
    const float* Wq   = (const float*)d_in[3];
    const float* Wk   = (const float*)d_in[4];
    const float* Wv   = (const float*)d_in[5];
    const float* Wo   = (const float*)d_in[6];
    const float* ln1g = (const float*)d_in[7];
    const float* ln1b = (const float*)d_in[8];
    const float* ln2g = (const float*)d_in[9];
    const float* ln2b = (const float*)d_in[10];
    const void*  mq   = d_in[11];
    const void*  mk   = d_in[12];
    float* out = (float*)d_out;

    void *pQp, *pAt, *pX, *pH, *pAh, *pAl, *pIh, *pIh2, *pWh, *pWl, *pQb, *pKb, *pVb;
    cudaGetSymbolAddress(&pQp, g_Qp);
    cudaGetSymbolAddress(&pAt, g_attn);
    cudaGetSymbolAddress(&pX,  g_X);
    cudaGetSymbolAddress(&pH,  g_Hb);
    cudaGetSymbolAddress(&pAh, g_Ah);
    cudaGetSymbolAddress(&pAl, g_Al);
    cudaGetSymbolAddress(&pIh, g_Ih);
    cudaGetSymbolAddress(&pIh2, g_Ih2);
    cudaGetSymbolAddress(&pWh, g_Wh);
    cudaGetSymbolAddress(&pWl, g_Wl);
    cudaGetSymbolAddress(&pQb, g_Qb);
    cudaGetSymbolAddress(&pKb, g_Kb);
    cudaGetSymbolAddress(&pVb, g_Vb);
    __nv_bfloat16* Ahp = (__nv_bfloat16*)pAh;
    __nv_bfloat16* Alp = (__nv_bfloat16*)pAl;
    __nv_bfloat16* Ihp = (__nv_bfloat16*)pIh;
    __nv_bfloat16* Ih2p = (__nv_bfloat16*)pIh2;
    __nv_bfloat16* Whp = (__nv_bfloat16*)pWh;
    __nv_bfloat16* Wlp = (__nv_bfloat16*)pWl;
    const int WSZ = DIMC * DIMC;
    const int WN4 = WSZ / 4;          // 262144
    const int AN4 = ROWS * DIMC / 4;  // 1048576

    prep_mask_kernel<<<1, 256>>>(mq, mk);

    // weights: Wq, Wo hi+lo; Wk, Wv hi only (one batched launch)
    {
        ConvJobs4 jw;
        jw.j[0] = {Wq, Whp + 0 * (size_t)WSZ, Wlp + 0 * (size_t)WSZ, WN4};
        jw.j[1] = {Wk, Whp + 1 * (size_t)WSZ, (__nv_bfloat16*)nullptr, WN4};
        jw.j[2] = {Wv, Whp + 2 * (size_t)WSZ, (__nv_bfloat16*)nullptr, WN4};
        jw.j[3] = {Wo, Whp + 3 * (size_t)WSZ, Wlp + 3 * (size_t)WSZ, WN4};
        conv_batch<<<dim3(WN4 / 256, 1, 4), 256>>>(jw);
    }
    // inputs: Q hi+lo; K, V hi only (one batched launch)
    {
        ConvJobs4 ji;
        ji.j[0] = {Q, Ahp, Alp, AN4};
        ji.j[1] = {K, Ihp, (__nv_bfloat16*)nullptr, AN4};
        ji.j[2] = {V, Ih2p, (__nv_bfloat16*)nullptr, AN4};
        ji.j[3] = {Q, Ahp, (__nv_bfloat16*)nullptr, 0};   // inert
        conv_batch<<<dim3(AN4 / 256, 1, 3), 256>>>(ji);
    }

    const size_t g3smem = 2 * BUFB;   // 81920 -> 2 CTAs/SM
    cudaFuncSetAttribute(gemm_mma3, cudaFuncAttributeMaxDynamicSharedMemorySize,
                         (int)g3smem);
    const size_t g1smem = 2 * S1B;    // 73728 -> 2 CTAs/SM
    cudaFuncSetAttribute(gemm_mma1, cudaFuncAttributeMaxDynamicSharedMemorySize,
                         (int)g1smem);
    dim3 gg(DIMC / 128, ROWS / 128);  // (8, 32)

    // Q projection: full 3-pass (fp32 Qp feeds residual) + bf16 Qb for flash
    gemm_mma3<<<gg, 256, g3smem>>>(Ahp, Alp, Whp + 0 * (size_t)WSZ,
                                   Wlp + 0 * (size_t)WSZ, (float*)pQp,
                                   (__nv_bfloat16*)pQb);
    // K and V projections: 1-pass bf16 (outputs only ever consumed as bf16)
    gemm_mma1<<<dim3(8, 32, 2), 256, g1smem>>>(
        Ihp,  Whp + 1 * (size_t)WSZ, (__nv_bfloat16*)pKb,
        Ih2p, Whp + 2 * (size_t)WSZ, (__nv_bfloat16*)pVb);

    const size_t fsmem = FQTB + 2 * FSTGB;  // 93184
    cudaFuncSetAttribute(flash_mma, cudaFuncAttributeMaxDynamicSharedMemorySize,
                         (int)fsmem);
    flash_mma<<<dim3(SEQ / 128, NH, BB), 256, fsmem>>>(
        (const __nv_bfloat16*)pQb, (const __nv_bfloat16*)pKb,
        (const __nv_bfloat16*)pVb, (float*)pAt);

    ln1_kernel<<<ROWS, 256>>>((const float*)pQp, (const float*)pAt, ln1g, ln1b,
                              (float*)pX, Ahp, Alp);

    gemm_mma3<<<gg, 256, g3smem>>>(Ahp, Alp, Whp + 3 * (size_t)WSZ,
                                   Wlp + 3 * (size_t)WSZ, (float*)pH,
                                   (__nv_bfloat16*)nullptr);

    final_kernel<<<ROWS, 256>>>((const float*)pX, (const float*)pH, ln2g, ln2b, out);
}

// round 10
// speedup vs baseline: 5.4008x; 1.1481x over previous
#include <cuda_runtime.h>
#include <cuda_fp16.h>
#include <math.h>
#include <stdint.h>

#define BB   4
#define SEQ  1024
#define DIMC 1024
#define NH   16
#define DHD  64
#define ROWS (BB * SEQ)      // 4096

// ---------------- scratch (device globals: allocation-guard safe) ----------------
__device__ float g_Qp[ROWS * DIMC];
__device__ float g_attn[ROWS * DIMC];
__device__ float g_X[ROWS * DIMC];
__device__ float g_Hb[ROWS * DIMC];
__device__ int   g_maskQ[ROWS];
__device__ float g_maskKF[ROWS];    // 0 or -1e38 addend
// fp16 GEMM operands
__device__ __half g_Ah[ROWS * DIMC];   // A hi (Q input / X)
__device__ __half g_Al[ROWS * DIMC];   // A lo
__device__ __half g_Ih[ROWS * DIMC];   // K input hi
__device__ __half g_Ih2[ROWS * DIMC];  // V input hi
__device__ __half g_Wh[4][DIMC * DIMC];
// fp16 projected tensors for flash
__device__ __half g_Qb[ROWS * DIMC];
__device__ __half g_Kb[ROWS * DIMC];
__device__ __half g_Vb[ROWS * DIMC];

// ---------------- PTX helpers (base compute_103-safe only) ----------------
__device__ __forceinline__ uint32_t smem_u32(const void* p) {
    uint32_t a;
    asm("{ .reg .u64 t; cvta.to.shared.u64 t, %1; cvt.u32.u64 %0, t; }"
        : "=r"(a) : "l"(p));
    return a;
}

#define CP_ASYNC16(dst, src) \
    asm volatile("cp.async.cg.shared.global [%0], [%1], 16;" \
                 :: "r"(dst), "l"(src) : "memory")
#define CP_COMMIT()  asm volatile("cp.async.commit_group;" ::: "memory")
#define CP_WAIT(n)   asm volatile("cp.async.wait_group %0;" :: "n"(n) : "memory")

#define LDSM4(r0, r1, r2, r3, addr) \
    asm volatile("ldmatrix.sync.aligned.m8n8.x4.shared.b16 {%0,%1,%2,%3}, [%4];" \
                 : "=r"(r0), "=r"(r1), "=r"(r2), "=r"(r3) : "r"(addr))

#define LDSM4T(r0, r1, r2, r3, addr) \
    asm volatile("ldmatrix.sync.aligned.m8n8.x4.trans.shared.b16 {%0,%1,%2,%3}, [%4];" \
                 : "=r"(r0), "=r"(r1), "=r"(r2), "=r"(r3) : "r"(addr))

#define MMA_FP16(d, a, b0, b1) \
    asm volatile("mma.sync.aligned.m16n8k16.row.col.f32.f16.f16.f32 " \
                 "{%0,%1,%2,%3}, {%4,%5,%6,%7}, {%8,%9}, {%0,%1,%2,%3};" \
                 : "+f"((d)[0]), "+f"((d)[1]), "+f"((d)[2]), "+f"((d)[3]) \
                 : "r"((a)[0]), "r"((a)[1]), "r"((a)[2]), "r"((a)[3]), \
                   "r"(b0), "r"(b1))

__device__ __forceinline__ uint32_t packhf(float lo, float hi) {
    __half2 v = __floats2half2_rn(lo, hi);   // .x = lo, .y = hi
    return *(uint32_t*)&v;
}

// ---------------- mask canonicalization ----------------
__device__ __forceinline__ int mask_is_bytes(const unsigned int* w) {
    bool wordlike = true;
#pragma unroll
    for (int i = 0; i < 32; i++) {
        unsigned int v = w[i];
        if (v != 0u && v != 1u && v != 0x3F800000u) wordlike = false;
    }
    return wordlike ? 0 : 1;
}

__global__ void prep_mask_kernel(const void* mq, const void* mk) {
    int bq = mask_is_bytes((const unsigned int*)mq);
    int bk = mask_is_bytes((const unsigned int*)mk);
    for (int i = threadIdx.x; i < ROWS; i += blockDim.x) {
        int vq = bq ? (((const unsigned char*)mq)[i] != 0)
                    : (((const unsigned int*)mq)[i] != 0u);
        int vk = bk ? (((const unsigned char*)mk)[i] != 0)
                    : (((const unsigned int*)mk)[i] != 0u);
        g_maskQ[i]  = vq;
        g_maskKF[i] = vk ? -1e38f : 0.f;
    }
}

// ---------------- batched fp32 -> fp16 (hi [, lo]) conversion ----------------
struct ConvJob { const float* src; __half* hi; __half* lo; int n4; };
struct ConvJobs4 { ConvJob j[4]; };

__global__ __launch_bounds__(256) void conv_batch(ConvJobs4 jobs) {
    const ConvJob jb = jobs.j[blockIdx.z];
    int i = blockIdx.x * 256 + threadIdx.x;
    if (i >= jb.n4) return;
    float4 v = ((const float4*)jb.src)[i];
    __half h0 = __float2half_rn(v.x);
    __half h1 = __float2half_rn(v.y);
    __half h2 = __float2half_rn(v.z);
    __half h3 = __float2half_rn(v.w);
    ((__half2*)jb.hi)[2 * i]     = __half2(h0, h1);
    ((__half2*)jb.hi)[2 * i + 1] = __half2(h2, h3);
    if (jb.lo) {
        __half l0 = __float2half_rn(v.x - __half2float(h0));
        __half l1 = __float2half_rn(v.y - __half2float(h1));
        __half l2 = __float2half_rn(v.z - __half2float(h2));
        __half l3 = __float2half_rn(v.w - __half2float(h3));
        ((__half2*)jb.lo)[2 * i]     = __half2(l0, l1);
        ((__half2*)jb.lo)[2 * i + 1] = __half2(l2, l3);
    }
}

// ---------------- 2-pass split-fp16 GEMM (Q and Wo projections) ----------------
// C = (Ah + Al) * Bh^T, fp32 accum. Error = weight fp16 rounding (~2.8e-4).
// CTA 128x128, warp 32x64, K-chunk 32, 2-stage cp.async, 2 CTAs/SM.
#define MST   40
#define TILEB (128 * MST * 2)        // 10240
#define BUFB  (3 * TILEB)            // 30720 per stage (Ah, Al, Bh)
#define NCH   (DIMC / 32)            // 32

__device__ __forceinline__ void g2_load(
    uint32_t sbase, const __half* __restrict__ Ah,
    const __half* __restrict__ Al, const __half* __restrict__ Bh,
    int bm, int bn, int k0, int tid) {
#pragma unroll
    for (int h = 0; h < 2; h++) {
        int idx = tid + h * 256;
        int r = idx >> 2, q = idx & 3;
        uint32_t doff = (uint32_t)(r * (MST * 2) + q * 16);
        size_t ga = ((size_t)(bm + r) << 10) + k0 + (q << 3);
        size_t gb = ((size_t)(bn + r) << 10) + k0 + (q << 3);
        CP_ASYNC16(sbase + doff,             Ah + ga);
        CP_ASYNC16(sbase + TILEB + doff,     Al + ga);
        CP_ASYNC16(sbase + 2 * TILEB + doff, Bh + gb);
    }
}

__global__ __launch_bounds__(256, 2) void gemm_mma2(
    const __half* __restrict__ Ah, const __half* __restrict__ Al,
    const __half* __restrict__ Bh,
    float* __restrict__ Cf, __half* __restrict__ Cb) {
    extern __shared__ char sm[];
    const uint32_t base = smem_u32(sm);
    const int tid = threadIdx.x;
    const int bm = blockIdx.y * 128;
    const int bn = blockIdx.x * 128;
    const int warp = tid >> 5, lane = tid & 31;
    const int wm = warp & 3;
    const int wn = warp >> 2;

    float acc[2][8][4];
#pragma unroll
    for (int i = 0; i < 2; i++)
#pragma unroll
        for (int j = 0; j < 8; j++)
#pragma unroll
            for (int k = 0; k < 4; k++) acc[i][j][k] = 0.f;

    g2_load(base, Ah, Al, Bh, bm, bn, 0, tid);
    CP_COMMIT();

    const int a_row = (lane & 15);
    const int a_k   = (lane >> 4) * 8;
    const int b_row = (lane & 7) + ((lane >> 4) << 3);
    const int b_k   = ((lane >> 3) & 1) * 8;

    for (int c = 0; c < NCH; c++) {
        if (c + 1 < NCH) {
            g2_load(base + ((c + 1) & 1) * BUFB, Ah, Al, Bh,
                    bm, bn, (c + 1) * 32, tid);
            CP_COMMIT();
            CP_WAIT(1);
        } else {
            CP_WAIT(0);
        }
        __syncthreads();

        const uint32_t bu = base + (c & 1) * BUFB;
        const uint32_t tAh = bu;
        const uint32_t tAl = bu + TILEB;
        const uint32_t tBh = bu + 2 * TILEB;

#pragma unroll
        for (int ks = 0; ks < 2; ks++) {
            uint32_t ah[2][4], al[2][4];
            const int kk = ks * 16 + a_k;
#pragma unroll
            for (int mf = 0; mf < 2; mf++) {
                uint32_t ra = (uint32_t)((wm * 32 + mf * 16 + a_row) * (MST * 2) + kk * 2);
                LDSM4(ah[mf][0], ah[mf][1], ah[mf][2], ah[mf][3], tAh + ra);
                LDSM4(al[mf][0], al[mf][1], al[mf][2], al[mf][3], tAl + ra);
            }
#pragma unroll
            for (int nf4 = 0; nf4 < 4; nf4++) {
                uint32_t bh[4];
                uint32_t rb = (uint32_t)((wn * 64 + nf4 * 16 + b_row) * (MST * 2) +
                                         (ks * 16 + b_k) * 2);
                LDSM4(bh[0], bh[1], bh[2], bh[3], tBh + rb);
#pragma unroll
                for (int mf = 0; mf < 2; mf++) {
                    MMA_FP16(acc[mf][nf4 * 2],     ah[mf], bh[0], bh[1]);
                    MMA_FP16(acc[mf][nf4 * 2],     al[mf], bh[0], bh[1]);
                    MMA_FP16(acc[mf][nf4 * 2 + 1], ah[mf], bh[2], bh[3]);
                    MMA_FP16(acc[mf][nf4 * 2 + 1], al[mf], bh[2], bh[3]);
                }
            }
        }
        __syncthreads();
    }

#pragma unroll
    for (int mf = 0; mf < 2; mf++) {
        int r0 = bm + wm * 32 + mf * 16 + (lane >> 2);
#pragma unroll
        for (int nf = 0; nf < 8; nf++) {
            int cc = bn + wn * 64 + nf * 8 + (lane & 3) * 2;
            if (Cf) {
                *(float2*)&Cf[(size_t)r0 * DIMC + cc] =
                    make_float2(acc[mf][nf][0], acc[mf][nf][1]);
                *(float2*)&Cf[(size_t)(r0 + 8) * DIMC + cc] =
                    make_float2(acc[mf][nf][2], acc[mf][nf][3]);
            }
            if (Cb) {
                *(uint32_t*)&Cb[(size_t)r0 * DIMC + cc] =
                    packhf(acc[mf][nf][0], acc[mf][nf][1]);
                *(uint32_t*)&Cb[(size_t)(r0 + 8) * DIMC + cc] =
                    packhf(acc[mf][nf][2], acc[mf][nf][3]);
            }
        }
    }
}

// ---------------- 1-pass fp16 GEMM (K and V projections, batched) ----------------
// Cb = fp16(Ah * Bh^T). K-chunk 64, 2-stage (2 CTAs/SM). z selects job.
#define T1ST  72                      // halves per row (144 B)
#define T1B   (128 * T1ST * 2)        // 18432
#define S1B   (2 * T1B)               // 36864 per stage
#define NCH1  (DIMC / 64)             // 16

__device__ __forceinline__ void g1_load(
    uint32_t sbase, const __half* __restrict__ A,
    const __half* __restrict__ B, int bm, int bn, int k0, int tid) {
#pragma unroll
    for (int i = 0; i < 4; i++) {
        int idx = tid + i * 256;
        int r = idx >> 3, q = idx & 7;
        uint32_t doff = (uint32_t)(r * (T1ST * 2) + q * 16);
        CP_ASYNC16(sbase + doff,       A + (((size_t)(bm + r)) << 10) + k0 + (q << 3));
        CP_ASYNC16(sbase + T1B + doff, B + (((size_t)(bn + r)) << 10) + k0 + (q << 3));
    }
}

__global__ __launch_bounds__(256, 2) void gemm_mma1(
    const __half* __restrict__ A0, const __half* __restrict__ B0,
    __half* __restrict__ C0,
    const __half* __restrict__ A1, const __half* __restrict__ B1,
    __half* __restrict__ C1) {
    extern __shared__ char sm[];
    const uint32_t base = smem_u32(sm);
    const int tid = threadIdx.x;
    const int bm = blockIdx.y * 128;
    const int bn = blockIdx.x * 128;
    const __half* A = blockIdx.z ? A1 : A0;
    const __half* B = blockIdx.z ? B1 : B0;
    __half* Cb = blockIdx.z ? C1 : C0;
    const int warp = tid >> 5, lane = tid & 31;
    const int wm = warp & 3;
    const int wn = warp >> 2;

    float acc[2][8][4];
#pragma unroll
    for (int i = 0; i < 2; i++)
#pragma unroll
        for (int j = 0; j < 8; j++)
#pragma unroll
            for (int k = 0; k < 4; k++) acc[i][j][k] = 0.f;

    g1_load(base, A, B, bm, bn, 0, tid);
    CP_COMMIT();

    const int a_row = (lane & 15);
    const int a_c16 = (lane >> 4) * 16;
    const int b_row = (lane & 7) + ((lane >> 4) << 3);
    const int b_c16 = ((lane >> 3) & 1) * 16;

    for (int c = 0; c < NCH1; c++) {
        if (c + 1 < NCH1) {
            g1_load(base + ((c + 1) & 1) * S1B, A, B, bm, bn, (c + 1) * 64, tid);
            CP_COMMIT();
            CP_WAIT(1);
        } else {
            CP_WAIT(0);
        }
        __syncthreads();

        const uint32_t tA = base + (c & 1) * S1B;
        const uint32_t tB = tA + T1B;

#pragma unroll
        for (int ks = 0; ks < 4; ks++) {
            uint32_t ah[2][4];
#pragma unroll
            for (int mf = 0; mf < 2; mf++)
                LDSM4(ah[mf][0], ah[mf][1], ah[mf][2], ah[mf][3],
                      tA + (wm * 32 + mf * 16 + a_row) * (T1ST * 2) + ks * 32 + a_c16);
#pragma unroll
            for (int nf4 = 0; nf4 < 4; nf4++) {
                uint32_t bh[4];
                LDSM4(bh[0], bh[1], bh[2], bh[3],
                      tB + (wn * 64 + nf4 * 16 + b_row) * (T1ST * 2) + ks * 32 + b_c16);
#pragma unroll
                for (int mf = 0; mf < 2; mf++) {
                    MMA_FP16(acc[mf][nf4 * 2],     ah[mf], bh[0], bh[1]);
                    MMA_FP16(acc[mf][nf4 * 2 + 1], ah[mf], bh[2], bh[3]);
                }
            }
        }
        __syncthreads();
    }

#pragma unroll
    for (int mf = 0; mf < 2; mf++) {
        int r0 = bm + wm * 32 + mf * 16 + (lane >> 2);
#pragma unroll
        for (int nf = 0; nf < 8; nf++) {
            int cc = bn + wn * 64 + nf * 8 + (lane & 3) * 2;
            *(uint32_t*)&Cb[(size_t)r0 * DIMC + cc] =
                packhf(acc[mf][nf][0], acc[mf][nf][1]);
            *(uint32_t*)&Cb[(size_t)(r0 + 8) * DIMC + cc] =
                packhf(acc[mf][nf][2], acc[mf][nf][3]);
        }
    }
}

// ---------------- tensor-core flash attention (fp16) ----------------
#define FKST   144
#define FQTB   (128 * FKST)
#define FSTGB  (2 * FQTB + 512)
#define FSCL   0.03125f

__device__ __forceinline__ void flash_load_stage(
    uint32_t sb, const __half* __restrict__ Kb,
    const __half* __restrict__ Vb, const float* __restrict__ mKF,
    int bz, int h, int k0, int tid) {
#pragma unroll
    for (int i = 0; i < 4; i++) {
        int idx = tid + i * 256;
        int r = idx >> 3, cq = idx & 7;
        size_t go = ((size_t)(bz * SEQ + k0 + r)) * DIMC + h * DHD + cq * 8;
        uint32_t doff = (uint32_t)(r * FKST + cq * 16);
        CP_ASYNC16(sb + doff,        Kb + go);
        CP_ASYNC16(sb + FQTB + doff, Vb + go);
    }
    if (tid < 32)
        CP_ASYNC16(sb + 2 * FQTB + tid * 16, mKF + bz * SEQ + k0 + tid * 4);
}

__global__ __launch_bounds__(256) void flash_mma(
    const __half* __restrict__ Qb, const __half* __restrict__ Kb,
    const __half* __restrict__ Vb, float* __restrict__ Out) {
    extern __shared__ char sm[];
    const uint32_t qbase = smem_u32(sm);
    const uint32_t sbase = qbase + FQTB;
    const float* mKF = g_maskKF;

    const int tid = threadIdx.x;
    const int bz = blockIdx.z, h = blockIdx.y;
    const int q0 = blockIdx.x * 128;
    const int lane = tid & 31, wq = tid >> 5;

#pragma unroll
    for (int i = 0; i < 4; i++) {
        int idx = tid + i * 256;
        int r = idx >> 3, cq = idx & 7;
        CP_ASYNC16(qbase + r * FKST + cq * 16,
                   Qb + ((size_t)(bz * SEQ + q0 + r)) * DIMC + h * DHD + cq * 8);
    }
    flash_load_stage(sbase, Kb, Vb, mKF, bz, h, 0, tid);
    CP_COMMIT();
    CP_WAIT(0);
    __syncthreads();

    const int a_row = (lane & 15);
    const int a_c16 = (lane >> 4) * 16;
    const int b_row = (lane & 7) + ((lane >> 4) << 3);
    const int b_c16 = ((lane >> 3) & 1) * 16;

    float m0 = -1e38f, m1 = -1e38f, l0 = 0.f, l1 = 0.f;
    float o[8][4];
#pragma unroll
    for (int i = 0; i < 8; i++)
#pragma unroll
        for (int j = 0; j < 4; j++) o[i][j] = 0.f;
    uint32_t qa[4][4];
#pragma unroll
    for (int ks = 0; ks < 4; ks++)
        LDSM4(qa[ks][0], qa[ks][1], qa[ks][2], qa[ks][3],
              qbase + (wq * 16 + a_row) * FKST + ks * 32 + a_c16);

    for (int c = 0; c < SEQ / 128; c++) {
        if (c + 1 < SEQ / 128) {
            flash_load_stage(sbase + ((c + 1) & 1) * FSTGB, Kb, Vb, mKF,
                             bz, h, (c + 1) * 128, tid);
            CP_COMMIT();
        }

        const uint32_t Kt = sbase + (c & 1) * FSTGB;
        const uint32_t Vt = Kt + FQTB;
        const uint32_t Mq = Kt + 2 * FQTB;

        float s[16][4];
#pragma unroll
        for (int i = 0; i < 16; i++)
#pragma unroll
            for (int j = 0; j < 4; j++) s[i][j] = 0.f;

#pragma unroll
        for (int kb = 0; kb < 8; kb++) {
#pragma unroll
            for (int ks = 0; ks < 4; ks++) {
                uint32_t b0, b1, b2, b3;
                LDSM4(b0, b1, b2, b3,
                      Kt + (kb * 16 + b_row) * FKST + ks * 32 + b_c16);
                MMA_FP16(s[2 * kb],     qa[ks], b0, b1);
                MMA_FP16(s[2 * kb + 1], qa[ks], b2, b3);
            }
        }

#pragma unroll
        for (int nf = 0; nf < 16; nf++) {
            float2 ma;
            asm volatile("ld.shared.v2.f32 {%0,%1}, [%2];"
                         : "=f"(ma.x), "=f"(ma.y)
                         : "r"(Mq + (uint32_t)(nf * 32 + (lane & 3) * 8)));
            s[nf][0] += ma.x; s[nf][1] += ma.y;
            s[nf][2] += ma.x; s[nf][3] += ma.y;
        }

        float mx0 = m0, mx1 = m1;
#pragma unroll
        for (int nf = 0; nf < 16; nf++) {
            mx0 = fmaxf(mx0, fmaxf(s[nf][0], s[nf][1]));
            mx1 = fmaxf(mx1, fmaxf(s[nf][2], s[nf][3]));
        }
#pragma unroll
        for (int off = 1; off <= 2; off <<= 1) {
            mx0 = fmaxf(mx0, __shfl_xor_sync(0xffffffffu, mx0, off));
            mx1 = fmaxf(mx1, __shfl_xor_sync(0xffffffffu, mx1, off));
        }
        const float c0 = __expf((m0 - mx0) * FSCL);
        const float c1 = __expf((m1 - mx1) * FSCL);
        m0 = mx0; m1 = mx1;
        l0 *= c0; l1 *= c1;
#pragma unroll
        for (int nf = 0; nf < 8; nf++) {
            o[nf][0] *= c0; o[nf][1] *= c0;
            o[nf][2] *= c1; o[nf][3] *= c1;
        }

        const float mk0 = mx0 * FSCL, mk1 = mx1 * FSCL;
        float ls0 = 0.f, ls1 = 0.f;
#pragma unroll
        for (int nf = 0; nf < 16; nf++) {
            s[nf][0] = __expf(fmaf(s[nf][0], FSCL, -mk0));
            s[nf][1] = __expf(fmaf(s[nf][1], FSCL, -mk0));
            s[nf][2] = __expf(fmaf(s[nf][2], FSCL, -mk1));
            s[nf][3] = __expf(fmaf(s[nf][3], FSCL, -mk1));
            ls0 += s[nf][0] + s[nf][1];
            ls1 += s[nf][2] + s[nf][3];
        }
#pragma unroll
        for (int off = 1; off <= 2; off <<= 1) {
            ls0 += __shfl_xor_sync(0xffffffffu, ls0, off);
            ls1 += __shfl_xor_sync(0xffffffffu, ls1, off);
        }
        l0 += ls0; l1 += ls1;

#pragma unroll
        for (int kv = 0; kv < 8; kv++) {
            uint32_t pa[4];
            pa[0] = packhf(s[2 * kv][0],     s[2 * kv][1]);
            pa[1] = packhf(s[2 * kv][2],     s[2 * kv][3]);
            pa[2] = packhf(s[2 * kv + 1][0], s[2 * kv + 1][1]);
            pa[3] = packhf(s[2 * kv + 1][2], s[2 * kv + 1][3]);
#pragma unroll
            for (int dp = 0; dp < 4; dp++) {
                uint32_t v0, v1, v2, v3;
                LDSM4T(v0, v1, v2, v3,
                       Vt + (kv * 16 + a_row) * FKST + dp * 32 + a_c16);
                MMA_FP16(o[2 * dp],     pa, v0, v1);
                MMA_FP16(o[2 * dp + 1], pa, v2, v3);
            }
        }

        if (c + 1 < SEQ / 128) CP_WAIT(0);
        __syncthreads();
    }

    const float inv0 = 1.f / l0, inv1 = 1.f / l1;
    const int row0 = bz * SEQ + q0 + wq * 16 + (lane >> 2);
#pragma unroll
    for (int nf = 0; nf < 8; nf++) {
        int cc = h * DHD + nf * 8 + (lane & 3) * 2;
        *(float2*)&Out[(size_t)row0 * DIMC + cc] =
            make_float2(o[nf][0] * inv0, o[nf][1] * inv0);
        *(float2*)&Out[(size_t)(row0 + 8) * DIMC + cc] =
            make_float2(o[nf][2] * inv1, o[nf][3] * inv1);
    }
}

// ---------------- layernorm helpers ----------------
__device__ __forceinline__ void block_reduce2(float& s, float& ss) {
    __shared__ float r1[8], r2[8];
#pragma unroll
    for (int o = 16; o > 0; o >>= 1) {
        s  += __shfl_xor_sync(0xffffffffu, s, o);
        ss += __shfl_xor_sync(0xffffffffu, ss, o);
    }
    int w = threadIdx.x >> 5;
    if ((threadIdx.x & 31) == 0) { r1[w] = s; r2[w] = ss; }
    __syncthreads();
    s = 0.f; ss = 0.f;
#pragma unroll
    for (int i = 0; i < 8; i++) { s += r1[i]; ss += r2[i]; }
}

// LN1: X = LN(Qp + attn) (zeroed on masked rows); emits fp16 hi/lo of X.
__global__ __launch_bounds__(256) void ln1_kernel(const float* __restrict__ A,
                                                  const float* __restrict__ Bv,
                                                  const float* __restrict__ gm,
                                                  const float* __restrict__ be,
                                                  float* __restrict__ X,
                                                  __half* __restrict__ Xh,
                                                  __half* __restrict__ Xl) {
    const int row = blockIdx.x;
    float* xo = X + (size_t)row * DIMC;
    __half* xh = Xh + (size_t)row * DIMC;
    __half* xl = Xl + (size_t)row * DIMC;
    if (g_maskQ[row]) {
        for (int i = threadIdx.x; i < DIMC; i += 256) {
            xo[i] = 0.f;
            xh[i] = __float2half_rn(0.f);
            xl[i] = __float2half_rn(0.f);
        }
        return;
    }
    const float* a  = A + (size_t)row * DIMC;
    const float* bv = Bv + (size_t)row * DIMC;
    float vals[4];
    float s = 0.f, ss = 0.f;
#pragma unroll
    for (int t = 0; t < 4; t++) {
        int i = threadIdx.x + t * 256;
        float v = a[i] + bv[i];
        vals[t] = v; s += v; ss += v * v;
    }
    block_reduce2(s, ss);
    float mean = s * (1.f / DIMC);
    float var  = ss * (1.f / DIMC) - mean * mean;
    float rstd = rsqrtf(var + 1e-5f);
#pragma unroll
    for (int t = 0; t < 4; t++) {
        int i = threadIdx.x + t * 256;
        float v = (vals[t] - mean) * rstd * gm[i] + be[i];
        xo[i] = v;
        __half hh = __float2half_rn(v);
        xh[i] = hh;
        xl[i] = __float2half_rn(v - __half2float(hh));
    }
}

__device__ __forceinline__ float gelu_exact(float x) {
    return 0.5f * x * (1.f + erff(x * 0.70710678118654752f));
}

__global__ __launch_bounds__(256) void final_kernel(const float* __restrict__ X,
                                                    const float* __restrict__ Hx,
                                                    const float* __restrict__ gm,
                                                    const float* __restrict__ be,
                                                    float* __restrict__ out) {
    const int row = blockIdx.x;
    float* o = out + (size_t)row * DIMC;
    if (g_maskQ[row]) {
        for (int i = threadIdx.x; i < DIMC; i += 256) o[i] = 0.f;
        return;
    }
    const float* x = X + (size_t)row * DIMC;
    const float* hv = Hx + (size_t)row * DIMC;
    float vals[4];
    float s = 0.f, ss = 0.f;
#pragma unroll
    for (int t = 0; t < 4; t++) {
        int i = threadIdx.x + t * 256;
        float v = x[i] + gelu_exact(hv[i]);
        vals[t] = v; s += v; ss += v * v;
    }
    block_reduce2(s, ss);
    float mean = s * (1.f / DIMC);
    float var  = ss * (1.f / DIMC) - mean * mean;
    float rstd = rsqrtf(var + 1e-5f);
#pragma unroll
    for (int t = 0; t < 4; t++) {
        int i = threadIdx.x + t * 256;
        o[i] = (vals[t] - mean) * rstd * gm[i] + be[i];
    }
}

// ---------------- launch ----------------
extern "C" void kernel_launch(void* const* d_in, const int* in_sizes, int n_in,
                              void* d_out, int out_size) {
    const float* Q    = (const float*)d_in[0];
    const float* K    = (const float*)d_in[1];
    const float* V    = (const float*)d_in[2];
    const float* Wq   = (const float*)d_in[3];
    const float* Wk   = (const float*)d_in[4];
    const float* Wv   = (const float*)d_in[5];
    const float* Wo   = (const float*)d_in[6];
    const float* ln1g = (const float*)d_in[7];
    const float* ln1b = (const float*)d_in[8];
    const float* ln2g = (const float*)d_in[9];
    const float* ln2b = (const float*)d_in[10];
    const void*  mq   = d_in[11];
    const void*  mk   = d_in[12];
    float* out = (float*)d_out;

    void *pQp, *pAt, *pX, *pH, *pAh, *pAl, *pIh, *pIh2, *pWh, *pQb, *pKb, *pVb;
    cudaGetSymbolAddress(&pQp, g_Qp);
    cudaGetSymbolAddress(&pAt, g_attn);
    cudaGetSymbolAddress(&pX,  g_X);
    cudaGetSymbolAddress(&pH,  g_Hb);
    cudaGetSymbolAddress(&pAh, g_Ah);
    cudaGetSymbolAddress(&pAl, g_Al);
    cudaGetSymbolAddress(&pIh, g_Ih);
    cudaGetSymbolAddress(&pIh2, g_Ih2);
    cudaGetSymbolAddress(&pWh, g_Wh);
    cudaGetSymbolAddress(&pQb, g_Qb);
    cudaGetSymbolAddress(&pKb, g_Kb);
    cudaGetSymbolAddress(&pVb, g_Vb);
    __half* Ahp  = (__half*)pAh;
    __half* Alp  = (__half*)pAl;
    __half* Ihp  = (__half*)pIh;
    __half* Ih2p = (__half*)pIh2;
    __half* Whp  = (__half*)pWh;
    const int WSZ = DIMC * DIMC;
    const int WN4 = WSZ / 4;          // 262144
    const int AN4 = ROWS * DIMC / 4;  // 1048576

    prep_mask_kernel<<<1, 256>>>(mq, mk);

    // weights: all hi-only (error carried by the split-A side)
    {
        ConvJobs4 jw;
        jw.j[0] = {Wq, Whp + 0 * (size_t)WSZ, (__half*)nullptr, WN4};
        jw.j[1] = {Wk, Whp + 1 * (size_t)WSZ, (__half*)nullptr, WN4};
        jw.j[2] = {Wv, Whp + 2 * (size_t)WSZ, (__half*)nullptr, WN4};
        jw.j[3] = {Wo, Whp + 3 * (size_t)WSZ, (__half*)nullptr, WN4};
        conv_batch<<<dim3(WN4 / 256, 1, 4), 256>>>(jw);
    }
    // inputs: Q hi+lo; K, V hi only
    {
        ConvJobs4 ji;
        ji.j[0] = {Q, Ahp, Alp, AN4};
        ji.j[1] = {K, Ihp, (__half*)nullptr, AN4};
        ji.j[2] = {V, Ih2p, (__half*)nullptr, AN4};
        ji.j[3] = {Q, Ahp, (__half*)nullptr, 0};   // inert
        conv_batch<<<dim3(AN4 / 256, 1, 3), 256>>>(ji);
    }

    const size_t g2smem = 2 * BUFB;   // 61440 -> 2 CTAs/SM
    cudaFuncSetAttribute(gemm_mma2, cudaFuncAttributeMaxDynamicSharedMemorySize,
                         (int)g2smem);
    const size_t g1smem = 2 * S1B;    // 73728 -> 2 CTAs/SM
    cudaFuncSetAttribute(gemm_mma1, cudaFuncAttributeMaxDynamicSharedMemorySize,
                         (int)g1smem);
    dim3 gg(DIMC / 128, ROWS / 128);  // (8, 32)

    // Q projection: 2-pass split-A fp16 + fp32 Qp (residual) + fp16 Qb (flash)
    gemm_mma2<<<gg, 256, g2smem>>>(Ahp, Alp, Whp + 0 * (size_t)WSZ,
                                   (float*)pQp, (__half*)pQb);
    // K and V projections: 1-pass fp16
    gemm_mma1<<<dim3(8, 32, 2), 256, g1smem>>>(
        Ihp,  Whp + 1 * (size_t)WSZ, (__half*)pKb,
        Ih2p, Whp + 2 * (size_t)WSZ, (__half*)pVb);

    const size_t fsmem = FQTB + 2 * FSTGB;  // 93184
    cudaFuncSetAttribute(flash_mma, cudaFuncAttributeMaxDynamicSharedMemorySize,
                         (int)fsmem);
    flash_mma<<<dim3(SEQ / 128, NH, BB), 256, fsmem>>>(
        (const __half*)pQb, (const __half*)pKb,
        (const __half*)pVb, (float*)pAt);

    ln1_kernel<<<ROWS, 256>>>((const float*)pQp, (const float*)pAt, ln1g, ln1b,
                              (float*)pX, Ahp, Alp);

    // Wo projection: 2-pass split-A fp16, fp32 out for GELU path
    gemm_mma2<<<gg, 256, g2smem>>>(Ahp, Alp, Whp + 3 * (size_t)WSZ,
                                   (float*)pH, (__half*)nullptr);

    final_kernel<<<ROWS, 256>>>((const float*)pX, (const float*)pH, ln2g, ln2b, out);
}